// round 11
// baseline (speedup 1.0000x reference)
#include <cuda_runtime.h>
#include <cstdint>

// ============================================================================
// VocabularyAttention on GB300 (sm_103a), mma.sync m16n8k8 tf32 + cp.async.
// Fused-softmax decomposition (no standalone softmax pass):
//   1. xr = roundperm(x); wlr = roundperm(Wl); wvr = roundperm(Wv);
//      wvt = roundperm-transpose(Wv)   (pad V -> VPAD with zeros)
//   2. logits = xr @ wvr^T + bv  ; epilogue emits per-(row, 256-tile)
//      online-softmax partials (m_t, l_t)            [gemm_tn, epi 0]
//   3. combine partials -> per-row M and R=1/l       [combine_stats]
//   4. hp[z] = P @ wvt^T where P = exp(logits - M)*R is materialized
//      on the fly in the A-loader (LDG -> exp -> perm8 STS)   [gemm_pv]
//      then h = round(sum_z hp[z])
//   5. out = h @ wlr^T + bl                          [gemm_tn, epi 2]
// perm8 = within-8 K-permutation [0,4,1,5,2,6,3,7] => LDS.64 mma fragments.
// All scalar/float2 memory ops in the new paths (R8 crash hardening).
// ============================================================================

#define VOCAB 50257
#define VPAD  50432      // 197*256, divisible by 64
#define DDIM  768
#define MROWS 4096
#define SPLITK 4
#define KSPLIT (VPAD / SPLITK)   // 12608 = 197*64
#define NT1   (VPAD / 256)       // 197 logits column tiles

__device__ float g_logits[(size_t)MROWS * VPAD];   // ~826 MB
__device__ float g_wvt[(size_t)DDIM * VPAD];       // rounded, vocab perm8
__device__ float g_wvr[(size_t)VOCAB * DDIM];      // rounded, K perm8
__device__ float g_xr[(size_t)MROWS * DDIM];       // rounded, K perm8
__device__ float g_wlr[(size_t)DDIM * DDIM];       // rounded, K perm8
__device__ float g_hp[(size_t)SPLITK * MROWS * DDIM];
__device__ float g_h[(size_t)MROWS * DDIM];        // natural
__device__ float g_pm[(size_t)MROWS * NT1];        // per-tile max
__device__ float g_pl[(size_t)MROWS * NT1];        // per-tile expsum
__device__ float g_mxv[MROWS];                     // row max M
__device__ float g_rlv[MROWS];                     // row 1/l

// ---------------------------------------------------------------------------
__device__ __forceinline__ uint32_t smem_u32(const void* p) {
    uint32_t a;
    asm("{ .reg .u64 t; cvta.to.shared.u64 t, %1; cvt.u32.u64 %0, t; }"
        : "=r"(a) : "l"(p));
    return a;
}

__device__ __forceinline__ float tf32r(float f) {
    uint32_t r;
    asm("cvt.rna.tf32.f32 %0, %1;" : "=r"(r) : "f"(f));
    return __uint_as_float(r);
}

// position of logical k (0..7) in permuted order [0,4,1,5,2,6,3,7]
__device__ __forceinline__ int pos8(int k) { return ((k & 3) << 1) | (k >> 2); }

__device__ __forceinline__ void mma_tf32(float c[4],
                                         uint32_t a0, uint32_t a1,
                                         uint32_t a2, uint32_t a3,
                                         uint32_t b0, uint32_t b1) {
    asm volatile(
        "mma.sync.aligned.m16n8k8.row.col.f32.tf32.tf32.f32 "
        "{%0,%1,%2,%3}, {%4,%5,%6,%7}, {%8,%9}, {%0,%1,%2,%3};"
        : "+f"(c[0]), "+f"(c[1]), "+f"(c[2]), "+f"(c[3])
        : "r"(a0), "r"(a1), "r"(a2), "r"(a3), "r"(b0), "r"(b1));
}

constexpr int BK = 64;

// ============================================================================
// gemm_tn:  C[M,N] = A[M,K] @ B[N,K]^T, CTA 128x256, 8 warps, BK=64, 2-stage.
// epi_mode 0: +aux[col], cols >= nvalidB -> -1e30, store logits, and emit
//             per-(row, CTA-tile) softmax partials into pm/pl.
// epi_mode 2: +aux[col] (bias)
// epi_mode 3: plain store (split-K partials)
// ============================================================================
template<bool APERM>
__global__ void __launch_bounds__(256, 1)
gemm_tn(const float* __restrict__ A, long long lda,
        const float* __restrict__ B, long long ldb,
        float* __restrict__ C, long long ldc, long long c_zstride,
        int Kps, int nvalidB,
        const float* __restrict__ aux, int epi_mode,
        float* __restrict__ pm, float* __restrict__ pl, int ntiles)
{
    constexpr int AS = APERM ? 72 : 68;
    constexpr int BS = 72;
    constexpr int A_STAGE = 128 * AS;
    constexpr int B_STAGE = 256 * BS;

    extern __shared__ float sm[];
    float* sA = sm;
    float* sB = sm + 2 * A_STAGE;

    __shared__ float red_s[512];     // dedicated (no dynamic-pool aliasing)
    __shared__ float red2_s[512];

    const int tid  = threadIdx.x;
    const int wid  = tid >> 5;
    const int lane = tid & 31;
    const int g    = lane >> 2;
    const int t    = lane & 3;
    const int wm   = wid >> 2;
    const int wn   = wid & 3;
    const int m0   = blockIdx.x * 128;
    const int n0   = blockIdx.y * 256;

    const long long koff = (long long)blockIdx.z * Kps;
    A += koff;
    B += koff;
    C += (long long)blockIdx.z * c_zstride;

    auto load_tiles = [&](int c, int s) {
        const float* Ab = A + (size_t)m0 * lda + (size_t)c * BK;
        const float* Bb = B + (size_t)c * BK;
        const uint32_t sAa = smem_u32(sA + s * A_STAGE);
        const uint32_t sBa = smem_u32(sB + s * B_STAGE);
        #pragma unroll
        for (int q = 0; q < 8; ++q) {
            int idx = tid + q * 256;
            int r = idx >> 4, j = idx & 15;
            const float* gp = Ab + (size_t)r * lda + j * 4;
            uint32_t da = sAa + (uint32_t)(r * AS + j * 4) * 4;
            asm volatile("cp.async.cg.shared.global [%0], [%1], 16;"
                         :: "r"(da), "l"(gp) : "memory");
        }
        #pragma unroll
        for (int q = 0; q < 16; ++q) {
            int idx = tid + q * 256;
            int r = idx >> 4, j = idx & 15;
            int gn = n0 + r;
            int ok = (gn < nvalidB);
            const float* gq = Bb + (size_t)(ok ? gn : 0) * ldb + j * 4;
            uint32_t db = sBa + (uint32_t)(r * BS + j * 4) * 4;
            int sz = ok ? 16 : 0;
            asm volatile("cp.async.cg.shared.global [%0], [%1], 16, %2;"
                         :: "r"(db), "l"(gq), "r"(sz) : "memory");
        }
        asm volatile("cp.async.commit_group;" ::: "memory");
    };

    float acc[4][8][4];
    #pragma unroll
    for (int i = 0; i < 4; ++i)
        #pragma unroll
        for (int j = 0; j < 8; ++j)
            #pragma unroll
            for (int k = 0; k < 4; ++k) acc[i][j][k] = 0.f;

    const int NCH = Kps / BK;
    load_tiles(0, 0);

    for (int c = 0; c < NCH; ++c) {
        if (c + 1 < NCH) {
            load_tiles(c + 1, (c + 1) & 1);
            asm volatile("cp.async.wait_group 1;" ::: "memory");
        } else {
            asm volatile("cp.async.wait_group 0;" ::: "memory");
        }
        __syncthreads();

        const int s = c & 1;
        const uint32_t* tA = reinterpret_cast<const uint32_t*>(sA + s * A_STAGE);
        const uint32_t* tB = reinterpret_cast<const uint32_t*>(sB + s * B_STAGE);

        #pragma unroll
        for (int ks = 0; ks < 8; ++ks) {
            const int kb = ks * 8;
            uint2 bf[8];
            #pragma unroll
            for (int ni = 0; ni < 8; ++ni) {
                int col = wn * 64 + ni * 8 + g;
                bf[ni] = *reinterpret_cast<const uint2*>(tB + col * BS + kb + 2 * t);
            }
            #pragma unroll
            for (int mi = 0; mi < 4; ++mi) {
                int rr = wm * 64 + mi * 16 + g;
                uint32_t a0, a1, a2, a3;
                if (APERM) {
                    uint2 qa = *reinterpret_cast<const uint2*>(tA + rr * AS + kb + 2 * t);
                    uint2 qb = *reinterpret_cast<const uint2*>(tA + (rr + 8) * AS + kb + 2 * t);
                    a0 = qa.x; a2 = qa.y; a1 = qb.x; a3 = qb.y;
                } else {
                    a0 = tA[rr * AS + kb + t];
                    a2 = tA[rr * AS + kb + t + 4];
                    a1 = tA[(rr + 8) * AS + kb + t];
                    a3 = tA[(rr + 8) * AS + kb + t + 4];
                }
                #pragma unroll
                for (int ni = 0; ni < 8; ++ni)
                    mma_tf32(acc[mi][ni], a0, a1, a2, a3, bf[ni].x, bf[ni].y);
            }
        }
        __syncthreads();
    }

    if (epi_mode == 0) {
        // ---- logits store + per-tile softmax partials ----
        float mx8[4][2];
        #pragma unroll
        for (int mi = 0; mi < 4; ++mi) { mx8[mi][0] = -3e38f; mx8[mi][1] = -3e38f; }
        #pragma unroll
        for (int mi = 0; mi < 4; ++mi) {
            const int rr = m0 + wm * 64 + mi * 16 + g;
            #pragma unroll
            for (int ni = 0; ni < 8; ++ni) {
                const int col = n0 + wn * 64 + ni * 8 + 2 * t;
                float b0 = (col     < nvalidB) ? aux[col]     : 0.f;
                float b1 = (col + 1 < nvalidB) ? aux[col + 1] : 0.f;
                float v0 = acc[mi][ni][0] + b0, v1 = acc[mi][ni][1] + b1;
                float v2 = acc[mi][ni][2] + b0, v3 = acc[mi][ni][3] + b1;
                if (col     >= nvalidB) { v0 = -1e30f; v2 = -1e30f; }
                if (col + 1 >= nvalidB) { v1 = -1e30f; v3 = -1e30f; }
                acc[mi][ni][0] = v0; acc[mi][ni][1] = v1;
                acc[mi][ni][2] = v2; acc[mi][ni][3] = v3;
                C[(size_t)rr * ldc + col]           = v0;
                C[(size_t)rr * ldc + col + 1]       = v1;
                C[(size_t)(rr + 8) * ldc + col]     = v2;
                C[(size_t)(rr + 8) * ldc + col + 1] = v3;
                mx8[mi][0] = fmaxf(mx8[mi][0], fmaxf(v0, v1));
                mx8[mi][1] = fmaxf(mx8[mi][1], fmaxf(v2, v3));
            }
        }
        // quad (t) max reduce
        #pragma unroll
        for (int mi = 0; mi < 4; ++mi)
            #pragma unroll
            for (int h = 0; h < 2; ++h) {
                float m = mx8[mi][h];
                m = fmaxf(m, __shfl_xor_sync(0xffffffffu, m, 1));
                m = fmaxf(m, __shfl_xor_sync(0xffffffffu, m, 2));
                mx8[mi][h] = m;
            }
        if (t == 0) {
            #pragma unroll
            for (int mi = 0; mi < 4; ++mi)
                #pragma unroll
                for (int h = 0; h < 2; ++h)
                    red_s[(wm * 64 + mi * 16 + h * 8 + g) * 4 + wn] = mx8[mi][h];
        }
        __syncthreads();
        float mf[4][2];
        #pragma unroll
        for (int mi = 0; mi < 4; ++mi)
            #pragma unroll
            for (int h = 0; h < 2; ++h) {
                int rl = wm * 64 + mi * 16 + h * 8 + g;
                mf[mi][h] = fmaxf(fmaxf(red_s[rl * 4 + 0], red_s[rl * 4 + 1]),
                                  fmaxf(red_s[rl * 4 + 2], red_s[rl * 4 + 3]));
            }
        float s8[4][2];
        #pragma unroll
        for (int mi = 0; mi < 4; ++mi) { s8[mi][0] = 0.f; s8[mi][1] = 0.f; }
        #pragma unroll
        for (int mi = 0; mi < 4; ++mi)
            #pragma unroll
            for (int ni = 0; ni < 8; ++ni) {
                s8[mi][0] += __expf(acc[mi][ni][0] - mf[mi][0])
                           + __expf(acc[mi][ni][1] - mf[mi][0]);
                s8[mi][1] += __expf(acc[mi][ni][2] - mf[mi][1])
                           + __expf(acc[mi][ni][3] - mf[mi][1]);
            }
        #pragma unroll
        for (int mi = 0; mi < 4; ++mi)
            #pragma unroll
            for (int h = 0; h < 2; ++h) {
                float s = s8[mi][h];
                s += __shfl_xor_sync(0xffffffffu, s, 1);
                s += __shfl_xor_sync(0xffffffffu, s, 2);
                s8[mi][h] = s;
            }
        if (t == 0) {
            #pragma unroll
            for (int mi = 0; mi < 4; ++mi)
                #pragma unroll
                for (int h = 0; h < 2; ++h)
                    red2_s[(wm * 64 + mi * 16 + h * 8 + g) * 4 + wn] = s8[mi][h];
        }
        __syncthreads();
        if (wn == 0 && t == 0) {
            #pragma unroll
            for (int mi = 0; mi < 4; ++mi)
                #pragma unroll
                for (int h = 0; h < 2; ++h) {
                    int rl = wm * 64 + mi * 16 + h * 8 + g;
                    float l = red2_s[rl * 4 + 0] + red2_s[rl * 4 + 1]
                            + red2_s[rl * 4 + 2] + red2_s[rl * 4 + 3];
                    size_t idx = (size_t)(m0 + rl) * ntiles + blockIdx.y;
                    pm[idx] = mf[mi][h];
                    pl[idx] = l;
                }
        }
        return;
    }

    // ---- epilogue modes 2/3 ----
    #pragma unroll
    for (int mi = 0; mi < 4; ++mi) {
        const int rr = m0 + wm * 64 + mi * 16 + g;
        #pragma unroll
        for (int ni = 0; ni < 8; ++ni) {
            const int col = n0 + wn * 64 + ni * 8 + 2 * t;
            float v0 = acc[mi][ni][0], v1 = acc[mi][ni][1];
            float v2 = acc[mi][ni][2], v3 = acc[mi][ni][3];
            if (epi_mode == 2) {
                float b0 = aux[col], b1 = aux[col + 1];
                v0 += b0; v1 += b1; v2 += b0; v3 += b1;
            }
            C[(size_t)rr * ldc + col]           = v0;
            C[(size_t)rr * ldc + col + 1]       = v1;
            C[(size_t)(rr + 8) * ldc + col]     = v2;
            C[(size_t)(rr + 8) * ldc + col + 1] = v3;
        }
    }
}

// ============================================================================
// combine_stats: per row, M and R=1/l from NT1 (m_t, l_t) tile partials.
// One warp per row; scalar stores.
// ============================================================================
__global__ void __launch_bounds__(256)
combine_stats(const float* __restrict__ pm, const float* __restrict__ pl,
              float* __restrict__ mxv, float* __restrict__ rlv)
{
    const int row  = blockIdx.x * 8 + (threadIdx.x >> 5);
    const int lane = threadIdx.x & 31;
    const float* pmr = pm + (size_t)row * NT1;
    const float* plr = pl + (size_t)row * NT1;

    float m = -3e38f;
    for (int i = lane; i < NT1; i += 32) m = fmaxf(m, pmr[i]);
    #pragma unroll
    for (int o = 16; o > 0; o >>= 1)
        m = fmaxf(m, __shfl_xor_sync(0xffffffffu, m, o));

    float l = 0.f;
    for (int i = lane; i < NT1; i += 32) l += plr[i] * __expf(pmr[i] - m);
    #pragma unroll
    for (int o = 16; o > 0; o >>= 1)
        l += __shfl_xor_sync(0xffffffffu, l, o);

    if (lane == 0) { mxv[row] = m; rlv[row] = 1.0f / l; }
}

// ============================================================================
// gemm_pv: hp[z] = P @ B^T with P = exp(logits - M)*R applied in the A-loader
// (float2 LDG prefetch -> exp -> tf32 round -> perm8 float2 STS).
// B via cp.async (perm8). CTA 128x256, 8 warps, BK=64, 2-stage.
// ============================================================================
__global__ void __launch_bounds__(256, 1)
gemm_pv(const float* __restrict__ A, long long lda,
        const float* __restrict__ B, long long ldb,
        float* __restrict__ C, long long ldc, long long c_zstride,
        int Kps,
        const float* __restrict__ mxv, const float* __restrict__ rlv)
{
    constexpr int AS = 72;
    constexpr int BS = 72;
    constexpr int A_STAGE = 128 * AS;
    constexpr int B_STAGE = 256 * BS;

    extern __shared__ float sm[];
    float* sA = sm;
    float* sB = sm + 2 * A_STAGE;

    const int tid  = threadIdx.x;
    const int wid  = tid >> 5;
    const int lane = tid & 31;
    const int g    = lane >> 2;
    const int t    = lane & 3;
    const int wm   = wid >> 2;
    const int wn   = wid & 3;
    const int m0   = blockIdx.x * 128;
    const int n0   = blockIdx.y * 256;

    const long long koff = (long long)blockIdx.z * Kps;
    A += koff;
    B += koff;
    C += (long long)blockIdx.z * c_zstride;

    // per-thread rows are fixed across chunks: r_q = (tid + q*256) >> 3
    float Mq[4], Rq[4];
    #pragma unroll
    for (int q = 0; q < 4; ++q) {
        int r = m0 + ((tid + q * 256) >> 3);
        Mq[q] = mxv[r];
        Rq[q] = rlv[r];
    }

    float2 lbuf[4][4];
    auto ldg_A = [&](int c) {
        const float* Ab = A + (size_t)c * BK;
        #pragma unroll
        for (int q = 0; q < 4; ++q) {
            int idx = tid + q * 256;
            int r = idx >> 3, j8 = idx & 7;
            const float* gp = Ab + (size_t)(m0 + r) * lda + j8 * 8;
            lbuf[q][0] = *reinterpret_cast<const float2*>(gp);
            lbuf[q][1] = *reinterpret_cast<const float2*>(gp + 2);
            lbuf[q][2] = *reinterpret_cast<const float2*>(gp + 4);
            lbuf[q][3] = *reinterpret_cast<const float2*>(gp + 6);
        }
    };
    auto sts_A = [&](int s) {
        float* base = sA + s * A_STAGE;
        #pragma unroll
        for (int q = 0; q < 4; ++q) {
            int idx = tid + q * 256;
            int r = idx >> 3, j8 = idx & 7;
            const float M = Mq[q], R = Rq[q];
            float e0 = tf32r(__expf(lbuf[q][0].x - M) * R);
            float e1 = tf32r(__expf(lbuf[q][0].y - M) * R);
            float e2 = tf32r(__expf(lbuf[q][1].x - M) * R);
            float e3 = tf32r(__expf(lbuf[q][1].y - M) * R);
            float e4 = tf32r(__expf(lbuf[q][2].x - M) * R);
            float e5 = tf32r(__expf(lbuf[q][2].y - M) * R);
            float e6 = tf32r(__expf(lbuf[q][3].x - M) * R);
            float e7 = tf32r(__expf(lbuf[q][3].y - M) * R);
            float* dst = base + r * AS + j8 * 8;
            // perm8 pack [0,4,1,5,2,6,3,7]
            *reinterpret_cast<float2*>(dst)     = make_float2(e0, e4);
            *reinterpret_cast<float2*>(dst + 2) = make_float2(e1, e5);
            *reinterpret_cast<float2*>(dst + 4) = make_float2(e2, e6);
            *reinterpret_cast<float2*>(dst + 6) = make_float2(e3, e7);
        }
    };
    auto load_B = [&](int c, int s) {
        const float* Bb = B + (size_t)c * BK;
        const uint32_t sBa = smem_u32(sB + s * B_STAGE);
        #pragma unroll
        for (int q = 0; q < 16; ++q) {
            int idx = tid + q * 256;
            int r = idx >> 4, j = idx & 15;
            const float* gq = Bb + (size_t)(n0 + r) * ldb + j * 4;
            uint32_t db = sBa + (uint32_t)(r * BS + j * 4) * 4;
            asm volatile("cp.async.cg.shared.global [%0], [%1], 16;"
                         :: "r"(db), "l"(gq) : "memory");
        }
        asm volatile("cp.async.commit_group;" ::: "memory");
    };

    float acc[4][8][4];
    #pragma unroll
    for (int i = 0; i < 4; ++i)
        #pragma unroll
        for (int j = 0; j < 8; ++j)
            #pragma unroll
            for (int k = 0; k < 4; ++k) acc[i][j][k] = 0.f;

    const int NCH = Kps / BK;
    ldg_A(0);
    load_B(0, 0);
    sts_A(0);

    for (int c = 0; c < NCH; ++c) {
        const int s = c & 1;
        if (c + 1 < NCH) {
            ldg_A(c + 1);                      // prefetch into registers
            load_B(c + 1, s ^ 1);
            asm volatile("cp.async.wait_group 1;" ::: "memory");
        } else {
            asm volatile("cp.async.wait_group 0;" ::: "memory");
        }
        __syncthreads();

        const uint32_t* tA = reinterpret_cast<const uint32_t*>(sA + s * A_STAGE);
        const uint32_t* tB = reinterpret_cast<const uint32_t*>(sB + s * B_STAGE);

        #pragma unroll
        for (int ks = 0; ks < 8; ++ks) {
            const int kb = ks * 8;
            uint2 bf[8];
            #pragma unroll
            for (int ni = 0; ni < 8; ++ni) {
                int col = wn * 64 + ni * 8 + g;
                bf[ni] = *reinterpret_cast<const uint2*>(tB + col * BS + kb + 2 * t);
            }
            #pragma unroll
            for (int mi = 0; mi < 4; ++mi) {
                int rr = wm * 64 + mi * 16 + g;
                uint2 qa = *reinterpret_cast<const uint2*>(tA + rr * AS + kb + 2 * t);
                uint2 qb = *reinterpret_cast<const uint2*>(tA + (rr + 8) * AS + kb + 2 * t);
                #pragma unroll
                for (int ni = 0; ni < 8; ++ni)
                    mma_tf32(acc[mi][ni], qa.x, qb.x, qa.y, qb.y,
                             bf[ni].x, bf[ni].y);
            }
        }

        if (c + 1 < NCH) sts_A(s ^ 1);   // stage s^1 not read this iteration
        __syncthreads();
    }

    #pragma unroll
    for (int mi = 0; mi < 4; ++mi) {
        const int rr = m0 + wm * 64 + mi * 16 + g;
        #pragma unroll
        for (int ni = 0; ni < 8; ++ni) {
            const int col = n0 + wn * 64 + ni * 8 + 2 * t;
            C[(size_t)rr * ldc + col]           = acc[mi][ni][0];
            C[(size_t)rr * ldc + col + 1]       = acc[mi][ni][1];
            C[(size_t)(rr + 8) * ldc + col]     = acc[mi][ni][2];
            C[(size_t)(rr + 8) * ldc + col + 1] = acc[mi][ni][3];
        }
    }
}

// ============================================================================
// prep kernels
// ============================================================================
__global__ void __launch_bounds__(256)
round_copy_perm(const float* __restrict__ in, float* __restrict__ out,
                long long n)
{
    long long i8 = ((long long)blockIdx.x * 256 + threadIdx.x) * 8;
    if (i8 >= n) return;
    float4 u = *reinterpret_cast<const float4*>(in + i8);
    float4 v = *reinterpret_cast<const float4*>(in + i8 + 4);
    float4 o0 = make_float4(tf32r(u.x), tf32r(v.x), tf32r(u.y), tf32r(v.y));
    float4 o1 = make_float4(tf32r(u.z), tf32r(v.z), tf32r(u.w), tf32r(v.w));
    *reinterpret_cast<float4*>(out + i8)     = o0;
    *reinterpret_cast<float4*>(out + i8 + 4) = o1;
}

__global__ void __launch_bounds__(256)
transpose_wv(const float* __restrict__ Wv, float* __restrict__ WvT)
{
    __shared__ float tt[32][33];
    const int v0 = blockIdx.x * 32;
    const int d0 = blockIdx.y * 32;
    const int tx = threadIdx.x & 31;
    const int ty = threadIdx.x >> 5;
    #pragma unroll
    for (int i = 0; i < 32; i += 8) {
        int v = v0 + ty + i;
        tt[ty + i][tx] = (v < VOCAB) ? tf32r(Wv[(size_t)v * DDIM + d0 + tx]) : 0.f;
    }
    __syncthreads();
    const int pcol = v0 + (tx & 24) + pos8(tx & 7);
    #pragma unroll
    for (int i = 0; i < 32; i += 8)
        WvT[(size_t)(d0 + ty + i) * VPAD + pcol] = tt[tx][ty + i];
}

__global__ void __launch_bounds__(256)
reduce_splitk(const float* __restrict__ hp, float* __restrict__ h)
{
    const size_t MD = (size_t)MROWS * DDIM;
    size_t i = ((size_t)blockIdx.x * 256 + threadIdx.x) * 4;
    float4 u = *reinterpret_cast<const float4*>(hp + i);
    #pragma unroll
    for (int z = 1; z < SPLITK; ++z) {
        float4 b = *reinterpret_cast<const float4*>(hp + z * MD + i);
        u.x += b.x; u.y += b.y; u.z += b.z; u.w += b.w;
    }
    u.x = tf32r(u.x); u.y = tf32r(u.y); u.z = tf32r(u.z); u.w = tf32r(u.w);
    *reinterpret_cast<float4*>(h + i) = u;
}

// ============================================================================
// host launcher
// ============================================================================
extern "C" void kernel_launch(void* const* d_in, const int* in_sizes, int n_in,
                              void* d_out, int out_size)
{
    const float* x  = (const float*)d_in[0];
    const float* Wv = (const float*)d_in[1];
    const float* bv = (const float*)d_in[2];
    const float* Wl = (const float*)d_in[3];
    const float* bl = (const float*)d_in[4];
    float* out = (float*)d_out;

    void *p_logits, *p_wvt, *p_wvr, *p_xr, *p_wlr, *p_hp, *p_h,
         *p_pm, *p_pl, *p_mx, *p_rl;
    cudaGetSymbolAddress(&p_logits, g_logits);
    cudaGetSymbolAddress(&p_wvt,    g_wvt);
    cudaGetSymbolAddress(&p_wvr,    g_wvr);
    cudaGetSymbolAddress(&p_xr,     g_xr);
    cudaGetSymbolAddress(&p_wlr,    g_wlr);
    cudaGetSymbolAddress(&p_hp,     g_hp);
    cudaGetSymbolAddress(&p_h,      g_h);
    cudaGetSymbolAddress(&p_pm,     g_pm);
    cudaGetSymbolAddress(&p_pl,     g_pl);
    cudaGetSymbolAddress(&p_mx,     g_mxv);
    cudaGetSymbolAddress(&p_rl,     g_rlv);
    float* logits = (float*)p_logits;
    float* wvt    = (float*)p_wvt;
    float* wvr    = (float*)p_wvr;
    float* xr     = (float*)p_xr;
    float* wlr    = (float*)p_wlr;
    float* hp     = (float*)p_hp;
    float* h      = (float*)p_h;
    float* pm     = (float*)p_pm;
    float* pl     = (float*)p_pl;
    float* mxv    = (float*)p_mx;
    float* rlv    = (float*)p_rl;

    const int SMEM_P = 2 * (128 * 72 + 256 * 72) * 4;   // 221184
    const int SMEM_N = 2 * (128 * 68 + 256 * 72) * 4;   // 217088
    static bool attr_set = false;
    if (!attr_set) {
        cudaFuncSetAttribute(gemm_tn<true>,
            cudaFuncAttributeMaxDynamicSharedMemorySize, SMEM_P);
        cudaFuncSetAttribute(gemm_tn<false>,
            cudaFuncAttributeMaxDynamicSharedMemorySize, SMEM_N);
        cudaFuncSetAttribute(gemm_pv,
            cudaFuncAttributeMaxDynamicSharedMemorySize, SMEM_P);
        attr_set = true;
    }

    // 1) prep
    const long long nX = (long long)MROWS * DDIM;
    const long long nL = (long long)DDIM * DDIM;
    const long long nV = (long long)VOCAB * DDIM;
    round_copy_perm<<<(int)((nX / 8 + 255) / 256), 256>>>(x, xr, nX);
    round_copy_perm<<<(int)((nL / 8 + 255) / 256), 256>>>(Wl, wlr, nL);
    round_copy_perm<<<(int)((nV / 8 + 255) / 256), 256>>>(Wv, wvr, nV);
    transpose_wv<<<dim3(VPAD / 32, DDIM / 32), 256>>>(Wv, wvt);

    // 2) logits + softmax partials
    gemm_tn<true><<<dim3(MROWS / 128, NT1, 1), 256, SMEM_P>>>(
        xr, DDIM, wvr, DDIM, logits, VPAD, 0, DDIM, VOCAB, bv, 0,
        pm, pl, NT1);

    // 3) combine -> M, 1/l
    combine_stats<<<MROWS / 8, 256>>>(pm, pl, mxv, rlv);

    // 4) hp[z] = P @ wvt^T (exp fused in loader), then h = round(sum)
    gemm_pv<<<dim3(MROWS / 128, DDIM / 256, SPLITK), 256, SMEM_P>>>(
        logits, VPAD, wvt, VPAD, hp, DDIM, (long long)MROWS * DDIM,
        KSPLIT, mxv, rlv);
    reduce_splitk<<<MROWS * DDIM / 1024, 256>>>(hp, h);

    // 5) out = h @ wlr^T + bl
    gemm_tn<false><<<dim3(MROWS / 128, DDIM / 256, 1), 256, SMEM_N>>>(
        h, DDIM, wlr, DDIM, out, DDIM, 0, DDIM, DDIM, bl, 2,
        nullptr, nullptr, 0);
}

// round 13
// speedup vs baseline: 1.0452x; 1.0452x over previous
#include <cuda_runtime.h>
#include <cstdint>

// ============================================================================
// VocabularyAttention on GB300 (sm_103a), mma.sync m16n8k8 tf32 + cp.async.
//   1. xr = roundperm(x); wlr = roundperm(Wl); wvr = roundperm(Wv);
//      wvt = roundperm-transpose(Wv)   (pad V -> VPAD with zeros)
//   2. logits = xr @ wvr^T + bv ; epilogue emits per-(row, 256-tile)
//      online-softmax partials (m_t, l_t)            [gemm_tn, epi 0]
//   3. combine partials -> per-row M and R=1/l       [combine_stats]
//   4. apply: probs = tf32r(exp(logit - M) * R), written PERM8 in place
//   5. hp[z] = probs @ wvt^T (split-K=4), h = round(sum hp)
//   6. out = h @ wlr^T + bl
// perm8 = within-8 K-permutation [0,4,1,5,2,6,3,7] => LDS.64 mma fragments.
// ============================================================================

#define VOCAB 50257
#define VPAD  50432      // 197*256, divisible by 64
#define DDIM  768
#define MROWS 4096
#define SPLITK 4
#define KSPLIT (VPAD / SPLITK)   // 12608 = 197*64
#define NT1   (VPAD / 256)       // 197 logits column tiles

__device__ float g_logits[(size_t)MROWS * VPAD];   // logits -> probs (perm8)
__device__ float g_wvt[(size_t)DDIM * VPAD];       // rounded, vocab perm8
__device__ float g_wvr[(size_t)VOCAB * DDIM];      // rounded, K perm8
__device__ float g_xr[(size_t)MROWS * DDIM];       // rounded, K perm8
__device__ float g_wlr[(size_t)DDIM * DDIM];       // rounded, K perm8
__device__ float g_hp[(size_t)SPLITK * MROWS * DDIM];
__device__ float g_h[(size_t)MROWS * DDIM];        // rounded, K perm8
__device__ float g_pm[(size_t)MROWS * NT1];        // per-tile max
__device__ float g_pl[(size_t)MROWS * NT1];        // per-tile expsum
__device__ float g_mxv[MROWS];                     // row max M
__device__ float g_rlv[MROWS];                     // row 1/l

// ---------------------------------------------------------------------------
__device__ __forceinline__ uint32_t smem_u32(const void* p) {
    uint32_t a;
    asm("{ .reg .u64 t; cvta.to.shared.u64 t, %1; cvt.u32.u64 %0, t; }"
        : "=r"(a) : "l"(p));
    return a;
}

__device__ __forceinline__ float tf32r(float f) {
    uint32_t r;
    asm("cvt.rna.tf32.f32 %0, %1;" : "=r"(r) : "f"(f));
    return __uint_as_float(r);
}

// position of logical k (0..7) in permuted order [0,4,1,5,2,6,3,7]
__device__ __forceinline__ int pos8(int k) { return ((k & 3) << 1) | (k >> 2); }

__device__ __forceinline__ void mma_tf32(float c[4],
                                         uint32_t a0, uint32_t a1,
                                         uint32_t a2, uint32_t a3,
                                         uint32_t b0, uint32_t b1) {
    asm volatile(
        "mma.sync.aligned.m16n8k8.row.col.f32.tf32.tf32.f32 "
        "{%0,%1,%2,%3}, {%4,%5,%6,%7}, {%8,%9}, {%0,%1,%2,%3};"
        : "+f"(c[0]), "+f"(c[1]), "+f"(c[2]), "+f"(c[3])
        : "r"(a0), "r"(a1), "r"(a2), "r"(a3), "r"(b0), "r"(b1));
}

constexpr int BK = 64;

// ============================================================================
// gemm_tn:  C[M,N] = A[M,K] @ B[N,K]^T, CTA 128x256, 8 warps, BK=64, 2-stage.
// epi_mode 0: +aux[col], cols >= nvalidB -> -1e30, store logits (float2),
//             and emit per-(row, CTA-tile) softmax partials into pm/pl.
// epi_mode 2: +aux[col] (bias) ; epi_mode 3: plain store (split-K partials)
// ============================================================================
template<bool APERM>
__global__ void __launch_bounds__(256, 1)
gemm_tn(const float* __restrict__ A, long long lda,
        const float* __restrict__ B, long long ldb,
        float* __restrict__ C, long long ldc, long long c_zstride,
        int Kps, int nvalidB,
        const float* __restrict__ aux, int epi_mode,
        float* __restrict__ pm, float* __restrict__ pl, int ntiles)
{
    constexpr int AS = APERM ? 72 : 68;
    constexpr int BS = 72;
    constexpr int A_STAGE = 128 * AS;
    constexpr int B_STAGE = 256 * BS;

    extern __shared__ float sm[];
    float* sA = sm;
    float* sB = sm + 2 * A_STAGE;

    __shared__ float red_s[512];     // dedicated static (no pool aliasing)
    __shared__ float red2_s[512];

    const int tid  = threadIdx.x;
    const int wid  = tid >> 5;
    const int lane = tid & 31;
    const int g    = lane >> 2;
    const int t    = lane & 3;
    const int wm   = wid >> 2;
    const int wn   = wid & 3;
    const int m0   = blockIdx.x * 128;
    const int n0   = blockIdx.y * 256;

    const long long koff = (long long)blockIdx.z * Kps;
    A += koff;
    B += koff;
    C += (long long)blockIdx.z * c_zstride;

    auto load_tiles = [&](int c, int s) {
        const float* Ab = A + (size_t)m0 * lda + (size_t)c * BK;
        const float* Bb = B + (size_t)c * BK;
        const uint32_t sAa = smem_u32(sA + s * A_STAGE);
        const uint32_t sBa = smem_u32(sB + s * B_STAGE);
        #pragma unroll
        for (int q = 0; q < 8; ++q) {
            int idx = tid + q * 256;
            int r = idx >> 4, j = idx & 15;
            const float* gp = Ab + (size_t)r * lda + j * 4;
            uint32_t da = sAa + (uint32_t)(r * AS + j * 4) * 4;
            asm volatile("cp.async.cg.shared.global [%0], [%1], 16;"
                         :: "r"(da), "l"(gp) : "memory");
        }
        #pragma unroll
        for (int q = 0; q < 16; ++q) {
            int idx = tid + q * 256;
            int r = idx >> 4, j = idx & 15;
            int gn = n0 + r;
            int ok = (gn < nvalidB);
            const float* gq = Bb + (size_t)(ok ? gn : 0) * ldb + j * 4;
            uint32_t db = sBa + (uint32_t)(r * BS + j * 4) * 4;
            int sz = ok ? 16 : 0;
            asm volatile("cp.async.cg.shared.global [%0], [%1], 16, %2;"
                         :: "r"(db), "l"(gq), "r"(sz) : "memory");
        }
        asm volatile("cp.async.commit_group;" ::: "memory");
    };

    float acc[4][8][4];
    #pragma unroll
    for (int i = 0; i < 4; ++i)
        #pragma unroll
        for (int j = 0; j < 8; ++j)
            #pragma unroll
            for (int k = 0; k < 4; ++k) acc[i][j][k] = 0.f;

    const int NCH = Kps / BK;
    load_tiles(0, 0);

    for (int c = 0; c < NCH; ++c) {
        if (c + 1 < NCH) {
            load_tiles(c + 1, (c + 1) & 1);
            asm volatile("cp.async.wait_group 1;" ::: "memory");
        } else {
            asm volatile("cp.async.wait_group 0;" ::: "memory");
        }
        __syncthreads();

        const int s = c & 1;
        const uint32_t* tA = reinterpret_cast<const uint32_t*>(sA + s * A_STAGE);
        const uint32_t* tB = reinterpret_cast<const uint32_t*>(sB + s * B_STAGE);

        #pragma unroll
        for (int ks = 0; ks < 8; ++ks) {
            const int kb = ks * 8;
            uint2 bf[8];
            #pragma unroll
            for (int ni = 0; ni < 8; ++ni) {
                int col = wn * 64 + ni * 8 + g;
                bf[ni] = *reinterpret_cast<const uint2*>(tB + col * BS + kb + 2 * t);
            }
            #pragma unroll
            for (int mi = 0; mi < 4; ++mi) {
                int rr = wm * 64 + mi * 16 + g;
                uint32_t a0, a1, a2, a3;
                if (APERM) {
                    uint2 qa = *reinterpret_cast<const uint2*>(tA + rr * AS + kb + 2 * t);
                    uint2 qb = *reinterpret_cast<const uint2*>(tA + (rr + 8) * AS + kb + 2 * t);
                    a0 = qa.x; a2 = qa.y; a1 = qb.x; a3 = qb.y;
                } else {
                    a0 = tA[rr * AS + kb + t];
                    a2 = tA[rr * AS + kb + t + 4];
                    a1 = tA[(rr + 8) * AS + kb + t];
                    a3 = tA[(rr + 8) * AS + kb + t + 4];
                }
                #pragma unroll
                for (int ni = 0; ni < 8; ++ni)
                    mma_tf32(acc[mi][ni], a0, a1, a2, a3, bf[ni].x, bf[ni].y);
            }
        }
        __syncthreads();
    }

    if (epi_mode == 0) {
        // ---- logits store (float2) + per-tile softmax partials ----
        float mx8[4][2];
        #pragma unroll
        for (int mi = 0; mi < 4; ++mi) { mx8[mi][0] = -3e38f; mx8[mi][1] = -3e38f; }
        #pragma unroll
        for (int mi = 0; mi < 4; ++mi) {
            const int rr = m0 + wm * 64 + mi * 16 + g;
            #pragma unroll
            for (int ni = 0; ni < 8; ++ni) {
                const int col = n0 + wn * 64 + ni * 8 + 2 * t;
                float b0 = (col     < nvalidB) ? aux[col]     : 0.f;
                float b1 = (col + 1 < nvalidB) ? aux[col + 1] : 0.f;
                float v0 = acc[mi][ni][0] + b0, v1 = acc[mi][ni][1] + b1;
                float v2 = acc[mi][ni][2] + b0, v3 = acc[mi][ni][3] + b1;
                if (col     >= nvalidB) { v0 = -1e30f; v2 = -1e30f; }
                if (col + 1 >= nvalidB) { v1 = -1e30f; v3 = -1e30f; }
                acc[mi][ni][0] = v0; acc[mi][ni][1] = v1;
                acc[mi][ni][2] = v2; acc[mi][ni][3] = v3;
                *reinterpret_cast<float2*>(C + (size_t)rr * ldc + col) =
                    make_float2(v0, v1);
                *reinterpret_cast<float2*>(C + (size_t)(rr + 8) * ldc + col) =
                    make_float2(v2, v3);
                mx8[mi][0] = fmaxf(mx8[mi][0], fmaxf(v0, v1));
                mx8[mi][1] = fmaxf(mx8[mi][1], fmaxf(v2, v3));
            }
        }
        #pragma unroll
        for (int mi = 0; mi < 4; ++mi)
            #pragma unroll
            for (int h = 0; h < 2; ++h) {
                float m = mx8[mi][h];
                m = fmaxf(m, __shfl_xor_sync(0xffffffffu, m, 1));
                m = fmaxf(m, __shfl_xor_sync(0xffffffffu, m, 2));
                mx8[mi][h] = m;
            }
        if (t == 0) {
            #pragma unroll
            for (int mi = 0; mi < 4; ++mi)
                #pragma unroll
                for (int h = 0; h < 2; ++h)
                    red_s[(wm * 64 + mi * 16 + h * 8 + g) * 4 + wn] = mx8[mi][h];
        }
        __syncthreads();
        float mf[4][2];
        #pragma unroll
        for (int mi = 0; mi < 4; ++mi)
            #pragma unroll
            for (int h = 0; h < 2; ++h) {
                int rl = wm * 64 + mi * 16 + h * 8 + g;
                mf[mi][h] = fmaxf(fmaxf(red_s[rl * 4 + 0], red_s[rl * 4 + 1]),
                                  fmaxf(red_s[rl * 4 + 2], red_s[rl * 4 + 3]));
            }
        float s8[4][2];
        #pragma unroll
        for (int mi = 0; mi < 4; ++mi) { s8[mi][0] = 0.f; s8[mi][1] = 0.f; }
        #pragma unroll
        for (int mi = 0; mi < 4; ++mi)
            #pragma unroll
            for (int ni = 0; ni < 8; ++ni) {
                s8[mi][0] += __expf(acc[mi][ni][0] - mf[mi][0])
                           + __expf(acc[mi][ni][1] - mf[mi][0]);
                s8[mi][1] += __expf(acc[mi][ni][2] - mf[mi][1])
                           + __expf(acc[mi][ni][3] - mf[mi][1]);
            }
        #pragma unroll
        for (int mi = 0; mi < 4; ++mi)
            #pragma unroll
            for (int h = 0; h < 2; ++h) {
                float s = s8[mi][h];
                s += __shfl_xor_sync(0xffffffffu, s, 1);
                s += __shfl_xor_sync(0xffffffffu, s, 2);
                s8[mi][h] = s;
            }
        if (t == 0) {
            #pragma unroll
            for (int mi = 0; mi < 4; ++mi)
                #pragma unroll
                for (int h = 0; h < 2; ++h)
                    red2_s[(wm * 64 + mi * 16 + h * 8 + g) * 4 + wn] = s8[mi][h];
        }
        __syncthreads();
        if (wn == 0 && t == 0) {
            #pragma unroll
            for (int mi = 0; mi < 4; ++mi)
                #pragma unroll
                for (int h = 0; h < 2; ++h) {
                    int rl = wm * 64 + mi * 16 + h * 8 + g;
                    float l = red2_s[rl * 4 + 0] + red2_s[rl * 4 + 1]
                            + red2_s[rl * 4 + 2] + red2_s[rl * 4 + 3];
                    size_t idx = (size_t)(m0 + rl) * ntiles + blockIdx.y;
                    pm[idx] = mf[mi][h];
                    pl[idx] = l;
                }
        }
        return;
    }

    // ---- epilogue modes 2/3: float2 stores ----
    #pragma unroll
    for (int mi = 0; mi < 4; ++mi) {
        const int rr = m0 + wm * 64 + mi * 16 + g;
        #pragma unroll
        for (int ni = 0; ni < 8; ++ni) {
            const int col = n0 + wn * 64 + ni * 8 + 2 * t;
            float v0 = acc[mi][ni][0], v1 = acc[mi][ni][1];
            float v2 = acc[mi][ni][2], v3 = acc[mi][ni][3];
            if (epi_mode == 2) {
                float b0 = aux[col], b1 = aux[col + 1];
                v0 += b0; v1 += b1; v2 += b0; v3 += b1;
            }
            *reinterpret_cast<float2*>(C + (size_t)rr * ldc + col) =
                make_float2(v0, v1);
            *reinterpret_cast<float2*>(C + (size_t)(rr + 8) * ldc + col) =
                make_float2(v2, v3);
        }
    }
}

// ============================================================================
// combine_stats: per row, M and R=1/l from NT1 (m_t, l_t) tile partials.
// ============================================================================
__global__ void __launch_bounds__(256)
combine_stats(const float* __restrict__ pm, const float* __restrict__ pl,
              float* __restrict__ mxv, float* __restrict__ rlv)
{
    const int row  = blockIdx.x * 8 + (threadIdx.x >> 5);
    const int lane = threadIdx.x & 31;
    const float* pmr = pm + (size_t)row * NT1;
    const float* plr = pl + (size_t)row * NT1;

    float m = -3e38f;
    for (int i = lane; i < NT1; i += 32) m = fmaxf(m, pmr[i]);
    #pragma unroll
    for (int o = 16; o > 0; o >>= 1)
        m = fmaxf(m, __shfl_xor_sync(0xffffffffu, m, o));

    float l = 0.f;
    for (int i = lane; i < NT1; i += 32) l += plr[i] * __expf(pmr[i] - m);
    #pragma unroll
    for (int o = 16; o > 0; o >>= 1)
        l += __shfl_xor_sync(0xffffffffu, l, o);

    if (lane == 0) { mxv[row] = m; rlv[row] = 1.0f / l; }
}

// ============================================================================
// apply_softmax: probs = tf32r(exp(logit - M) * R), perm8-packed, in place.
// One CTA per row; float4 reads, perm8 float4 writes.
// ============================================================================
__global__ void __launch_bounds__(256)
apply_softmax(float* __restrict__ L,
              const float* __restrict__ mxv, const float* __restrict__ rlv)
{
    const int row = blockIdx.x;
    float* rp = L + (size_t)row * VPAD;
    const float M = mxv[row];
    const float R = rlv[row];

    for (int i = threadIdx.x; i < VPAD / 8; i += 256) {
        float4 u = *reinterpret_cast<const float4*>(rp + i * 8);
        float4 v = *reinterpret_cast<const float4*>(rp + i * 8 + 4);
        float e0 = tf32r(__expf(u.x - M) * R);
        float e1 = tf32r(__expf(u.y - M) * R);
        float e2 = tf32r(__expf(u.z - M) * R);
        float e3 = tf32r(__expf(u.w - M) * R);
        float e4 = tf32r(__expf(v.x - M) * R);
        float e5 = tf32r(__expf(v.y - M) * R);
        float e6 = tf32r(__expf(v.z - M) * R);
        float e7 = tf32r(__expf(v.w - M) * R);
        *reinterpret_cast<float4*>(rp + i * 8)     = make_float4(e0, e4, e1, e5);
        *reinterpret_cast<float4*>(rp + i * 8 + 4) = make_float4(e2, e6, e3, e7);
    }
}

// ============================================================================
// prep kernels
// ============================================================================
__global__ void __launch_bounds__(256)
round_copy_perm(const float* __restrict__ in, float* __restrict__ out,
                long long n)
{
    long long i8 = ((long long)blockIdx.x * 256 + threadIdx.x) * 8;
    if (i8 >= n) return;
    float4 u = *reinterpret_cast<const float4*>(in + i8);
    float4 v = *reinterpret_cast<const float4*>(in + i8 + 4);
    float4 o0 = make_float4(tf32r(u.x), tf32r(v.x), tf32r(u.y), tf32r(v.y));
    float4 o1 = make_float4(tf32r(u.z), tf32r(v.z), tf32r(u.w), tf32r(v.w));
    *reinterpret_cast<float4*>(out + i8)     = o0;
    *reinterpret_cast<float4*>(out + i8 + 4) = o1;
}

__global__ void __launch_bounds__(256)
transpose_wv(const float* __restrict__ Wv, float* __restrict__ WvT)
{
    __shared__ float tt[32][33];
    const int v0 = blockIdx.x * 32;
    const int d0 = blockIdx.y * 32;
    const int tx = threadIdx.x & 31;
    const int ty = threadIdx.x >> 5;
    #pragma unroll
    for (int i = 0; i < 32; i += 8) {
        int v = v0 + ty + i;
        tt[ty + i][tx] = (v < VOCAB) ? tf32r(Wv[(size_t)v * DDIM + d0 + tx]) : 0.f;
    }
    __syncthreads();
    const int pcol = v0 + (tx & 24) + pos8(tx & 7);
    #pragma unroll
    for (int i = 0; i < 32; i += 8)
        WvT[(size_t)(d0 + ty + i) * VPAD + pcol] = tt[tx][ty + i];
}

// split-K reduction: h = roundperm(sum_z hp[z])  (h feeds GEMM3 APERM=true)
__global__ void __launch_bounds__(256)
reduce_splitk(const float* __restrict__ hp, float* __restrict__ h)
{
    const size_t MD = (size_t)MROWS * DDIM;
    size_t i8 = ((size_t)blockIdx.x * 256 + threadIdx.x) * 8;
    float4 u = *reinterpret_cast<const float4*>(hp + i8);
    float4 v = *reinterpret_cast<const float4*>(hp + i8 + 4);
    #pragma unroll
    for (int z = 1; z < SPLITK; ++z) {
        float4 bu = *reinterpret_cast<const float4*>(hp + z * MD + i8);
        float4 bv = *reinterpret_cast<const float4*>(hp + z * MD + i8 + 4);
        u.x += bu.x; u.y += bu.y; u.z += bu.z; u.w += bu.w;
        v.x += bv.x; v.y += bv.y; v.z += bv.z; v.w += bv.w;
    }
    float4 o0 = make_float4(tf32r(u.x), tf32r(v.x), tf32r(u.y), tf32r(v.y));
    float4 o1 = make_float4(tf32r(u.z), tf32r(v.z), tf32r(u.w), tf32r(v.w));
    *reinterpret_cast<float4*>(h + i8)     = o0;
    *reinterpret_cast<float4*>(h + i8 + 4) = o1;
}

// ============================================================================
// host launcher
// ============================================================================
extern "C" void kernel_launch(void* const* d_in, const int* in_sizes, int n_in,
                              void* d_out, int out_size)
{
    const float* x  = (const float*)d_in[0];
    const float* Wv = (const float*)d_in[1];
    const float* bv = (const float*)d_in[2];
    const float* Wl = (const float*)d_in[3];
    const float* bl = (const float*)d_in[4];
    float* out = (float*)d_out;

    void *p_logits, *p_wvt, *p_wvr, *p_xr, *p_wlr, *p_hp, *p_h,
         *p_pm, *p_pl, *p_mx, *p_rl;
    cudaGetSymbolAddress(&p_logits, g_logits);
    cudaGetSymbolAddress(&p_wvt,    g_wvt);
    cudaGetSymbolAddress(&p_wvr,    g_wvr);
    cudaGetSymbolAddress(&p_xr,     g_xr);
    cudaGetSymbolAddress(&p_wlr,    g_wlr);
    cudaGetSymbolAddress(&p_hp,     g_hp);
    cudaGetSymbolAddress(&p_h,      g_h);
    cudaGetSymbolAddress(&p_pm,     g_pm);
    cudaGetSymbolAddress(&p_pl,     g_pl);
    cudaGetSymbolAddress(&p_mx,     g_mxv);
    cudaGetSymbolAddress(&p_rl,     g_rlv);
    float* logits = (float*)p_logits;
    float* wvt    = (float*)p_wvt;
    float* wvr    = (float*)p_wvr;
    float* xr     = (float*)p_xr;
    float* wlr    = (float*)p_wlr;
    float* hp     = (float*)p_hp;
    float* h      = (float*)p_h;
    float* pm     = (float*)p_pm;
    float* pl     = (float*)p_pl;
    float* mxv    = (float*)p_mx;
    float* rlv    = (float*)p_rl;

    const int SMEM_P = 2 * (128 * 72 + 256 * 72) * 4;   // 221184
    static bool attr_set = false;
    if (!attr_set) {
        cudaFuncSetAttribute(gemm_tn<true>,
            cudaFuncAttributeMaxDynamicSharedMemorySize, SMEM_P);
        attr_set = true;
    }

    // 1) prep
    const long long nX = (long long)MROWS * DDIM;
    const long long nL = (long long)DDIM * DDIM;
    const long long nV = (long long)VOCAB * DDIM;
    round_copy_perm<<<(int)((nX / 8 + 255) / 256), 256>>>(x, xr, nX);
    round_copy_perm<<<(int)((nL / 8 + 255) / 256), 256>>>(Wl, wlr, nL);
    round_copy_perm<<<(int)((nV / 8 + 255) / 256), 256>>>(Wv, wvr, nV);
    transpose_wv<<<dim3(VPAD / 32, DDIM / 32), 256>>>(Wv, wvt);

    // 2) logits = xr @ wvr^T + bv  (+ per-tile softmax partials)
    gemm_tn<true><<<dim3(MROWS / 128, NT1, 1), 256, SMEM_P>>>(
        xr, DDIM, wvr, DDIM, logits, VPAD, 0, DDIM, VOCAB, bv, 0,
        pm, pl, NT1);

    // 3) combine -> M, 1/l
    combine_stats<<<MROWS / 8, 256>>>(pm, pl, mxv, rlv);

    // 4) apply: probs = exp(logit - M) * R  (perm8, in place)
    apply_softmax<<<MROWS, 256>>>(logits, mxv, rlv);

    // 5) hp[z] = probs @ wvt^T (split-K), then h = roundperm(sum)
    gemm_tn<true><<<dim3(MROWS / 128, DDIM / 256, SPLITK), 256, SMEM_P>>>(
        logits, VPAD, wvt, VPAD, hp, DDIM, (long long)MROWS * DDIM,
        KSPLIT, DDIM, nullptr, 3, nullptr, nullptr, 0);
    reduce_splitk<<<MROWS * DDIM / 2048, 256>>>(hp, h);

    // 6) out = h @ wlr^T + bl
    gemm_tn<true><<<dim3(MROWS / 128, DDIM / 256, 1), 256, SMEM_P>>>(
        h, DDIM, wlr, DDIM, out, DDIM, 0, DDIM, DDIM, bl, 2,
        nullptr, nullptr, 0);
}

// round 16
// speedup vs baseline: 1.8986x; 1.8165x over previous
#include <cuda_runtime.h>
#include <cuda_fp16.h>
#include <cstdint>

// ============================================================================
// VocabularyAttention on GB300 (sm_103a): fp16 mma.sync m16n8k16 (fp32 accum)
// + cp.async, 3-stage pipeline. fp16 mantissa (11 bits) == tf32 precision but
// 2x tensor rate and half the memory traffic.
//
//   1. prep: xr/wlr/wvr = fp16 perm16 copies; wvt = fp16 perm16 transpose
//   2. logits(fp32) = xr @ wvr^T + bv ; epilogue emits per-(row,256-tile)
//      online-softmax partials (m_t, l_t)
//   3. combine partials -> per-row M, R=1/l
//   4. apply: p16 = half(exp(logit - M) * R), perm16 layout
//   5. hp[z] = p16 @ wvt^T (split-K=4), h = half(sum hp) perm16
//   6. out = h @ wlr^T + bl
// perm16 (within 16 K-elems): [0,1,8,9,2,3,10,11,4,5,12,13,6,7,14,15]
//   => thread(t) fragment pair {k=2t,2t+1} ∪ {k=2t+8,2t+9} is one LDS.64.
// ============================================================================

#define VOCAB 50257
#define VPAD  50432      // 197*256, divisible by 64 and 16
#define DDIM  768
#define MROWS 4096
#define SPLITK 4
#define KSPLIT (VPAD / SPLITK)   // 12608, divisible by 64
#define NT1   (VPAD / 256)       // 197

__device__ float  g_logits[(size_t)MROWS * VPAD];   // fp32 logits
__device__ __half g_p16[(size_t)MROWS * VPAD];      // probs, perm16
__device__ __half g_wvt[(size_t)DDIM * VPAD];       // Wv^T, vocab perm16
__device__ __half g_wvr[(size_t)VOCAB * DDIM];      // Wv, K perm16
__device__ __half g_xr[(size_t)MROWS * DDIM];       // x, K perm16
__device__ __half g_wlr[(size_t)DDIM * DDIM];       // Wl, K perm16
__device__ float  g_hp[(size_t)SPLITK * MROWS * DDIM];
__device__ __half g_h[(size_t)MROWS * DDIM];        // h, K perm16
__device__ float  g_pm[(size_t)MROWS * NT1];
__device__ float  g_pl[(size_t)MROWS * NT1];
__device__ float  g_mxv[MROWS];
__device__ float  g_rlv[MROWS];

// ---------------------------------------------------------------------------
__device__ __forceinline__ uint32_t smem_u32(const void* p) {
    uint32_t a;
    asm("{ .reg .u64 t; cvta.to.shared.u64 t, %1; cvt.u32.u64 %0, t; }"
        : "=r"(a) : "l"(p));
    return a;
}

// position of logical k (0..15) in perm16 order
__device__ __host__ __forceinline__ int pos16(int k) {
    return 4 * ((k >> 1) & 3) + 2 * ((k >> 3) & 1) + (k & 1);
}

__device__ __forceinline__ uint32_t pack2(float a, float b) {
    __half2 h = __floats2half2_rn(a, b);
    return *reinterpret_cast<uint32_t*>(&h);
}

__device__ __forceinline__ void mma_f16(float c[4],
                                        uint32_t a0, uint32_t a1,
                                        uint32_t a2, uint32_t a3,
                                        uint32_t b0, uint32_t b1) {
    asm volatile(
        "mma.sync.aligned.m16n8k16.row.col.f32.f16.f16.f32 "
        "{%0,%1,%2,%3}, {%4,%5,%6,%7}, {%8,%9}, {%0,%1,%2,%3};"
        : "+f"(c[0]), "+f"(c[1]), "+f"(c[2]), "+f"(c[3])
        : "r"(a0), "r"(a1), "r"(a2), "r"(a3), "r"(b0), "r"(b1));
}

constexpr int BK   = 64;              // fp16 elems per chunk
constexpr int AS   = 80;              // smem row stride (fp16) -> 160B, CF
constexpr int BS   = 80;
constexpr int A_STAGE = 128 * AS;     // halves
constexpr int B_STAGE = 256 * BS;
constexpr int NSTAGE  = 3;
constexpr int GEMM_SMEM = NSTAGE * (A_STAGE + B_STAGE) * 2;  // 184320 B

// ============================================================================
// gemm_f16:  C[M,N] = A[M,K] @ B[N,K]^T  (A,B fp16 perm16; C fp32)
// CTA tile 128x256, 8 warps (2m x 4n), warp 64x64, BK=64, 3-stage, 1 sync.
// epi_mode 0: +aux[col], col>=nvalidB -> -1e30, store logits + pm/pl partials
// epi_mode 2: +aux[col]  ; epi_mode 3: plain store
// ============================================================================
__global__ void __launch_bounds__(256, 1)
gemm_f16(const __half* __restrict__ A, long long lda,
         const __half* __restrict__ B, long long ldb,
         float* __restrict__ C, long long ldc, long long c_zstride,
         int Kps, int nvalidB,
         const float* __restrict__ aux, int epi_mode,
         float* __restrict__ pm, float* __restrict__ pl, int ntiles)
{
    extern __shared__ __half smh[];
    __half* sA = smh;
    __half* sB = smh + NSTAGE * A_STAGE;

    __shared__ float red_s[512];
    __shared__ float red2_s[512];

    const int tid  = threadIdx.x;
    const int wid  = tid >> 5;
    const int lane = tid & 31;
    const int g    = lane >> 2;
    const int t    = lane & 3;
    const int wm   = wid >> 2;
    const int wn   = wid & 3;
    const int m0   = blockIdx.x * 128;
    const int n0   = blockIdx.y * 256;

    const long long koff = (long long)blockIdx.z * Kps;
    A += koff;
    B += koff;
    C += (long long)blockIdx.z * c_zstride;

    auto load_tiles = [&](int c, int s) {
        const __half* Ab = A + (size_t)m0 * lda + (size_t)c * BK;
        const __half* Bb = B + (size_t)c * BK;
        const uint32_t sAa = smem_u32(sA + s * A_STAGE);
        const uint32_t sBa = smem_u32(sB + s * B_STAGE);
        #pragma unroll
        for (int q = 0; q < 4; ++q) {                 // A: 128 rows x 8 16B
            int idx = tid + q * 256;
            int r = idx >> 3, j = idx & 7;
            const __half* gp = Ab + (size_t)r * lda + j * 8;
            uint32_t da = sAa + (uint32_t)(r * AS + j * 8) * 2;
            asm volatile("cp.async.cg.shared.global [%0], [%1], 16;"
                         :: "r"(da), "l"(gp) : "memory");
        }
        #pragma unroll
        for (int q = 0; q < 8; ++q) {                 // B: 256 rows x 8 16B
            int idx = tid + q * 256;
            int r = idx >> 3, j = idx & 7;
            int gn = n0 + r;
            int ok = (gn < nvalidB);
            const __half* gq = Bb + (size_t)(ok ? gn : 0) * ldb + j * 8;
            uint32_t db = sBa + (uint32_t)(r * BS + j * 8) * 2;
            int sz = ok ? 16 : 0;
            asm volatile("cp.async.cg.shared.global [%0], [%1], 16, %2;"
                         :: "r"(db), "l"(gq), "r"(sz) : "memory");
        }
        asm volatile("cp.async.commit_group;" ::: "memory");
    };

    float acc[4][8][4];
    #pragma unroll
    for (int i = 0; i < 4; ++i)
        #pragma unroll
        for (int j = 0; j < 8; ++j)
            #pragma unroll
            for (int k = 0; k < 4; ++k) acc[i][j][k] = 0.f;

    const int NCH = Kps / BK;
    load_tiles(0, 0);
    if (NCH > 1) load_tiles(1, 1);

    for (int c = 0; c < NCH; ++c) {
        if (c + 1 < NCH) {
            asm volatile("cp.async.wait_group 1;" ::: "memory");
        } else {
            asm volatile("cp.async.wait_group 0;" ::: "memory");
        }
        __syncthreads();
        if (c + 2 < NCH) load_tiles(c + 2, (c + 2) % NSTAGE);

        const int s = c % NSTAGE;
        const __half* tA = sA + s * A_STAGE;
        const __half* tB = sB + s * B_STAGE;

        #pragma unroll
        for (int ks = 0; ks < 4; ++ks) {              // 4 x k16 per BK=64
            const int kb = ks * 16 + 4 * t;           // perm16 pair offset
            uint2 bf[8];
            #pragma unroll
            for (int ni = 0; ni < 8; ++ni) {
                int col = wn * 64 + ni * 8 + g;
                bf[ni] = *reinterpret_cast<const uint2*>(tB + col * BS + kb);
            }
            #pragma unroll
            for (int mi = 0; mi < 4; ++mi) {
                int rr = wm * 64 + mi * 16 + g;
                // qa = {a0 (k 2t,2t+1), a2 (k 2t+8,2t+9)} row rr
                // qb = {a1, a3} row rr+8
                uint2 qa = *reinterpret_cast<const uint2*>(tA + rr * AS + kb);
                uint2 qb = *reinterpret_cast<const uint2*>(tA + (rr + 8) * AS + kb);
                #pragma unroll
                for (int ni = 0; ni < 8; ++ni)
                    mma_f16(acc[mi][ni], qa.x, qb.x, qa.y, qb.y,
                            bf[ni].x, bf[ni].y);
            }
        }
    }

    if (epi_mode == 0) {
        // ---- logits store (float2) + per-tile softmax partials ----
        float mx8[4][2];
        #pragma unroll
        for (int mi = 0; mi < 4; ++mi) { mx8[mi][0] = -3e38f; mx8[mi][1] = -3e38f; }
        #pragma unroll
        for (int mi = 0; mi < 4; ++mi) {
            const int rr = m0 + wm * 64 + mi * 16 + g;
            #pragma unroll
            for (int ni = 0; ni < 8; ++ni) {
                const int col = n0 + wn * 64 + ni * 8 + 2 * t;
                float b0 = (col     < nvalidB) ? aux[col]     : 0.f;
                float b1 = (col + 1 < nvalidB) ? aux[col + 1] : 0.f;
                float v0 = acc[mi][ni][0] + b0, v1 = acc[mi][ni][1] + b1;
                float v2 = acc[mi][ni][2] + b0, v3 = acc[mi][ni][3] + b1;
                if (col     >= nvalidB) { v0 = -1e30f; v2 = -1e30f; }
                if (col + 1 >= nvalidB) { v1 = -1e30f; v3 = -1e30f; }
                acc[mi][ni][0] = v0; acc[mi][ni][1] = v1;
                acc[mi][ni][2] = v2; acc[mi][ni][3] = v3;
                *reinterpret_cast<float2*>(C + (size_t)rr * ldc + col) =
                    make_float2(v0, v1);
                *reinterpret_cast<float2*>(C + (size_t)(rr + 8) * ldc + col) =
                    make_float2(v2, v3);
                mx8[mi][0] = fmaxf(mx8[mi][0], fmaxf(v0, v1));
                mx8[mi][1] = fmaxf(mx8[mi][1], fmaxf(v2, v3));
            }
        }
        #pragma unroll
        for (int mi = 0; mi < 4; ++mi)
            #pragma unroll
            for (int h = 0; h < 2; ++h) {
                float m = mx8[mi][h];
                m = fmaxf(m, __shfl_xor_sync(0xffffffffu, m, 1));
                m = fmaxf(m, __shfl_xor_sync(0xffffffffu, m, 2));
                mx8[mi][h] = m;
            }
        if (t == 0) {
            #pragma unroll
            for (int mi = 0; mi < 4; ++mi)
                #pragma unroll
                for (int h = 0; h < 2; ++h)
                    red_s[(wm * 64 + mi * 16 + h * 8 + g) * 4 + wn] = mx8[mi][h];
        }
        __syncthreads();
        float mf[4][2];
        #pragma unroll
        for (int mi = 0; mi < 4; ++mi)
            #pragma unroll
            for (int h = 0; h < 2; ++h) {
                int rl = wm * 64 + mi * 16 + h * 8 + g;
                mf[mi][h] = fmaxf(fmaxf(red_s[rl * 4 + 0], red_s[rl * 4 + 1]),
                                  fmaxf(red_s[rl * 4 + 2], red_s[rl * 4 + 3]));
            }
        float s8[4][2];
        #pragma unroll
        for (int mi = 0; mi < 4; ++mi) { s8[mi][0] = 0.f; s8[mi][1] = 0.f; }
        #pragma unroll
        for (int mi = 0; mi < 4; ++mi)
            #pragma unroll
            for (int ni = 0; ni < 8; ++ni) {
                s8[mi][0] += __expf(acc[mi][ni][0] - mf[mi][0])
                           + __expf(acc[mi][ni][1] - mf[mi][0]);
                s8[mi][1] += __expf(acc[mi][ni][2] - mf[mi][1])
                           + __expf(acc[mi][ni][3] - mf[mi][1]);
            }
        #pragma unroll
        for (int mi = 0; mi < 4; ++mi)
            #pragma unroll
            for (int h = 0; h < 2; ++h) {
                float s = s8[mi][h];
                s += __shfl_xor_sync(0xffffffffu, s, 1);
                s += __shfl_xor_sync(0xffffffffu, s, 2);
                s8[mi][h] = s;
            }
        if (t == 0) {
            #pragma unroll
            for (int mi = 0; mi < 4; ++mi)
                #pragma unroll
                for (int h = 0; h < 2; ++h)
                    red2_s[(wm * 64 + mi * 16 + h * 8 + g) * 4 + wn] = s8[mi][h];
        }
        __syncthreads();
        if (wn == 0 && t == 0) {
            #pragma unroll
            for (int mi = 0; mi < 4; ++mi)
                #pragma unroll
                for (int h = 0; h < 2; ++h) {
                    int rl = wm * 64 + mi * 16 + h * 8 + g;
                    float l = red2_s[rl * 4 + 0] + red2_s[rl * 4 + 1]
                            + red2_s[rl * 4 + 2] + red2_s[rl * 4 + 3];
                    size_t idx = (size_t)(m0 + rl) * ntiles + blockIdx.y;
                    pm[idx] = mf[mi][h];
                    pl[idx] = l;
                }
        }
        return;
    }

    // ---- epilogue modes 2/3 ----
    #pragma unroll
    for (int mi = 0; mi < 4; ++mi) {
        const int rr = m0 + wm * 64 + mi * 16 + g;
        #pragma unroll
        for (int ni = 0; ni < 8; ++ni) {
            const int col = n0 + wn * 64 + ni * 8 + 2 * t;
            float v0 = acc[mi][ni][0], v1 = acc[mi][ni][1];
            float v2 = acc[mi][ni][2], v3 = acc[mi][ni][3];
            if (epi_mode == 2) {
                float b0 = aux[col], b1 = aux[col + 1];
                v0 += b0; v1 += b1; v2 += b0; v3 += b1;
            }
            *reinterpret_cast<float2*>(C + (size_t)rr * ldc + col) =
                make_float2(v0, v1);
            *reinterpret_cast<float2*>(C + (size_t)(rr + 8) * ldc + col) =
                make_float2(v2, v3);
        }
    }
}

// ============================================================================
// combine_stats: per row, M and R=1/l from NT1 (m_t, l_t) tile partials.
// ============================================================================
__global__ void __launch_bounds__(256)
combine_stats(const float* __restrict__ pm, const float* __restrict__ pl,
              float* __restrict__ mxv, float* __restrict__ rlv)
{
    const int row  = blockIdx.x * 8 + (threadIdx.x >> 5);
    const int lane = threadIdx.x & 31;
    const float* pmr = pm + (size_t)row * NT1;
    const float* plr = pl + (size_t)row * NT1;

    float m = -3e38f;
    for (int i = lane; i < NT1; i += 32) m = fmaxf(m, pmr[i]);
    #pragma unroll
    for (int o = 16; o > 0; o >>= 1)
        m = fmaxf(m, __shfl_xor_sync(0xffffffffu, m, o));

    float l = 0.f;
    for (int i = lane; i < NT1; i += 32) l += plr[i] * __expf(pmr[i] - m);
    #pragma unroll
    for (int o = 16; o > 0; o >>= 1)
        l += __shfl_xor_sync(0xffffffffu, l, o);

    if (lane == 0) { mxv[row] = m; rlv[row] = 1.0f / l; }
}

// ============================================================================
// apply_softmax: p16 = half(exp(logit - M) * R), perm16 packed.
// One CTA per row; each thread handles one 16-elem group per step.
// ============================================================================
__global__ void __launch_bounds__(256)
apply_softmax(const float* __restrict__ L, __half* __restrict__ P,
              const float* __restrict__ mxv, const float* __restrict__ rlv)
{
    const int row = blockIdx.x;
    const float* rp = L + (size_t)row * VPAD;
    __half* op = P + (size_t)row * VPAD;
    const float M = mxv[row];
    const float R = rlv[row];

    for (int i = threadIdx.x; i < VPAD / 16; i += 256) {
        const float* src = rp + i * 16;
        float e[16];
        #pragma unroll
        for (int q = 0; q < 4; ++q) {
            float4 v = *reinterpret_cast<const float4*>(src + q * 4);
            e[q * 4 + 0] = __expf(v.x - M) * R;
            e[q * 4 + 1] = __expf(v.y - M) * R;
            e[q * 4 + 2] = __expf(v.z - M) * R;
            e[q * 4 + 3] = __expf(v.w - M) * R;
        }
        uint32_t o[8];
        #pragma unroll
        for (int tq = 0; tq < 4; ++tq) {
            o[tq * 2 + 0] = pack2(e[2 * tq],     e[2 * tq + 1]);
            o[tq * 2 + 1] = pack2(e[2 * tq + 8], e[2 * tq + 9]);
        }
        uint4* dst = reinterpret_cast<uint4*>(op + i * 16);
        dst[0] = make_uint4(o[0], o[1], o[2], o[3]);
        dst[1] = make_uint4(o[4], o[5], o[6], o[7]);
    }
}

// ============================================================================
// prep: fp32 -> fp16 perm16 copy (16 consecutive elems per thread)
// ============================================================================
__global__ void __launch_bounds__(256)
half_copy_perm(const float* __restrict__ in, __half* __restrict__ out,
               long long n)
{
    long long i16 = ((long long)blockIdx.x * 256 + threadIdx.x) * 16;
    if (i16 >= n) return;
    float e[16];
    #pragma unroll
    for (int q = 0; q < 4; ++q) {
        float4 v = *reinterpret_cast<const float4*>(in + i16 + q * 4);
        e[q * 4 + 0] = v.x; e[q * 4 + 1] = v.y;
        e[q * 4 + 2] = v.z; e[q * 4 + 3] = v.w;
    }
    uint32_t o[8];
    #pragma unroll
    for (int tq = 0; tq < 4; ++tq) {
        o[tq * 2 + 0] = pack2(e[2 * tq],     e[2 * tq + 1]);
        o[tq * 2 + 1] = pack2(e[2 * tq + 8], e[2 * tq + 9]);
    }
    uint4* dst = reinterpret_cast<uint4*>(out + i16);
    dst[0] = make_uint4(o[0], o[1], o[2], o[3]);
    dst[1] = make_uint4(o[4], o[5], o[6], o[7]);
}

// ============================================================================
// transpose_wv: wvt[d, perm16(v)] = half(Wv[v, d]), zero-padded to VPAD
// ============================================================================
__global__ void __launch_bounds__(256)
transpose_wv(const float* __restrict__ Wv, __half* __restrict__ WvT)
{
    __shared__ float tt[32][33];
    const int v0 = blockIdx.x * 32;
    const int d0 = blockIdx.y * 32;
    const int tx = threadIdx.x & 31;
    const int ty = threadIdx.x >> 5;
    #pragma unroll
    for (int i = 0; i < 32; i += 8) {
        int v = v0 + ty + i;
        tt[ty + i][tx] = (v < VOCAB) ? Wv[(size_t)v * DDIM + d0 + tx] : 0.f;
    }
    __syncthreads();
    const int pcol = v0 + (tx & 16) + pos16(tx & 15);
    #pragma unroll
    for (int i = 0; i < 32; i += 8)
        WvT[(size_t)(d0 + ty + i) * VPAD + pcol] = __float2half_rn(tt[tx][ty + i]);
}

// ============================================================================
// reduce_splitk: h = half(sum_z hp[z]), perm16 packed (16 elems/thread)
// ============================================================================
__global__ void __launch_bounds__(256)
reduce_splitk(const float* __restrict__ hp, __half* __restrict__ h)
{
    const size_t MD = (size_t)MROWS * DDIM;
    size_t i16 = ((size_t)blockIdx.x * 256 + threadIdx.x) * 16;
    float e[16];
    #pragma unroll
    for (int q = 0; q < 4; ++q) {
        float4 v = *reinterpret_cast<const float4*>(hp + i16 + q * 4);
        e[q * 4 + 0] = v.x; e[q * 4 + 1] = v.y;
        e[q * 4 + 2] = v.z; e[q * 4 + 3] = v.w;
    }
    #pragma unroll
    for (int z = 1; z < SPLITK; ++z) {
        #pragma unroll
        for (int q = 0; q < 4; ++q) {
            float4 v = *reinterpret_cast<const float4*>(hp + z * MD + i16 + q * 4);
            e[q * 4 + 0] += v.x; e[q * 4 + 1] += v.y;
            e[q * 4 + 2] += v.z; e[q * 4 + 3] += v.w;
        }
    }
    uint32_t o[8];
    #pragma unroll
    for (int tq = 0; tq < 4; ++tq) {
        o[tq * 2 + 0] = pack2(e[2 * tq],     e[2 * tq + 1]);
        o[tq * 2 + 1] = pack2(e[2 * tq + 8], e[2 * tq + 9]);
    }
    uint4* dst = reinterpret_cast<uint4*>(h + i16);
    dst[0] = make_uint4(o[0], o[1], o[2], o[3]);
    dst[1] = make_uint4(o[4], o[5], o[6], o[7]);
}

// ============================================================================
// host launcher
// ============================================================================
extern "C" void kernel_launch(void* const* d_in, const int* in_sizes, int n_in,
                              void* d_out, int out_size)
{
    const float* x  = (const float*)d_in[0];
    const float* Wv = (const float*)d_in[1];
    const float* bv = (const float*)d_in[2];
    const float* Wl = (const float*)d_in[3];
    const float* bl = (const float*)d_in[4];
    float* out = (float*)d_out;

    void *p_logits, *p_p16, *p_wvt, *p_wvr, *p_xr, *p_wlr, *p_hp, *p_h,
         *p_pm, *p_pl, *p_mx, *p_rl;
    cudaGetSymbolAddress(&p_logits, g_logits);
    cudaGetSymbolAddress(&p_p16,    g_p16);
    cudaGetSymbolAddress(&p_wvt,    g_wvt);
    cudaGetSymbolAddress(&p_wvr,    g_wvr);
    cudaGetSymbolAddress(&p_xr,     g_xr);
    cudaGetSymbolAddress(&p_wlr,    g_wlr);
    cudaGetSymbolAddress(&p_hp,     g_hp);
    cudaGetSymbolAddress(&p_h,      g_h);
    cudaGetSymbolAddress(&p_pm,     g_pm);
    cudaGetSymbolAddress(&p_pl,     g_pl);
    cudaGetSymbolAddress(&p_mx,     g_mxv);
    cudaGetSymbolAddress(&p_rl,     g_rlv);
    float*  logits = (float*)p_logits;
    __half* p16    = (__half*)p_p16;
    __half* wvt    = (__half*)p_wvt;
    __half* wvr    = (__half*)p_wvr;
    __half* xr     = (__half*)p_xr;
    __half* wlr    = (__half*)p_wlr;
    float*  hp     = (float*)p_hp;
    __half* h      = (__half*)p_h;
    float*  pm     = (float*)p_pm;
    float*  pl     = (float*)p_pl;
    float*  mxv    = (float*)p_mx;
    float*  rlv    = (float*)p_rl;

    static bool attr_set = false;
    if (!attr_set) {
        cudaFuncSetAttribute(gemm_f16,
            cudaFuncAttributeMaxDynamicSharedMemorySize, GEMM_SMEM);
        attr_set = true;
    }

    // 1) prep: fp16 perm16 copies + transpose
    const long long nX = (long long)MROWS * DDIM;
    const long long nL = (long long)DDIM * DDIM;
    const long long nV = (long long)VOCAB * DDIM;
    half_copy_perm<<<(int)((nX / 16 + 255) / 256), 256>>>(x, xr, nX);
    half_copy_perm<<<(int)((nL / 16 + 255) / 256), 256>>>(Wl, wlr, nL);
    half_copy_perm<<<(int)((nV / 16 + 255) / 256), 256>>>(Wv, wvr, nV);
    transpose_wv<<<dim3(VPAD / 32, DDIM / 32), 256>>>(Wv, wvt);

    // 2) logits = xr @ wvr^T + bv  (+ per-tile softmax partials)
    gemm_f16<<<dim3(MROWS / 128, NT1, 1), 256, GEMM_SMEM>>>(
        xr, DDIM, wvr, DDIM, logits, VPAD, 0, DDIM, VOCAB, bv, 0,
        pm, pl, NT1);

    // 3) combine -> M, 1/l
    combine_stats<<<MROWS / 8, 256>>>(pm, pl, mxv, rlv);

    // 4) apply: p16 = exp(logit - M) * R  (perm16)
    apply_softmax<<<MROWS, 256>>>(logits, p16, mxv, rlv);

    // 5) hp[z] = p16 @ wvt^T (split-K), h = half(sum) perm16
    gemm_f16<<<dim3(MROWS / 128, DDIM / 256, SPLITK), 256, GEMM_SMEM>>>(
        p16, VPAD, wvt, VPAD, hp, DDIM, (long long)MROWS * DDIM,
        KSPLIT, DDIM, nullptr, 3, nullptr, nullptr, 0);
    reduce_splitk<<<MROWS * DDIM / 4096, 256>>>(hp, h);

    // 6) out = h @ wlr^T + bl
    gemm_f16<<<dim3(MROWS / 128, DDIM / 256, 1), 256, GEMM_SMEM>>>(
        h, DDIM, wlr, DDIM, out, DDIM, 0, DDIM, DDIM, bl, 2,
        nullptr, nullptr, 0);
}

// round 17
// speedup vs baseline: 2.0923x; 1.1020x over previous
#include <cuda_runtime.h>
#include <cuda_fp16.h>
#include <cstdint>

// ============================================================================
// VocabularyAttention on GB300 (sm_103a): fp16 mma.sync m16n8k16 (fp32 accum)
// + cp.async 3-stage pipeline. No fp32 logits buffer:
//   1. prep: xr/wlr/wvr = fp16 perm16 copies; wvt = fp16 perm16 transpose
//   2. GEMM1: p_tile = fp16(exp(x@Wv^T + bv - m_tile)) stored perm16,
//      plus per-(row, 256-col-tile) partials (m_t, l_t)
//   3. combine partials -> per-row M, R=1/l
//   4. rescale: p *= exp(m_t - M) * R       (fp32 math, fp16 store)
//   5. hp[z] = p @ wvt^T (split-K=6, clamped), h = half(sum hp) perm16
//   6. out = h @ wlr^T + bl
// perm16 (within 16 K-elems): [0,1,8,9,2,3,10,11,4,5,12,13,6,7,14,15]
//   => thread(t) fragment pair {2t,2t+1} ∪ {2t+8,2t+9} is one LDS.64.
// ============================================================================

#define VOCAB 50257
#define VPAD  50432      // 197*256
#define DDIM  768
#define MROWS 4096
#define SPLITK 6
#define KSPL  8448       // 132*64 ; last slice = 50432-5*8448 = 8192 = 128*64
#define NT1   (VPAD / 256)       // 197

__device__ __half g_p16[(size_t)MROWS * VPAD];      // probs, perm16
__device__ __half g_wvt[(size_t)DDIM * VPAD];       // Wv^T, vocab perm16
__device__ __half g_wvr[(size_t)VOCAB * DDIM];      // Wv, K perm16
__device__ __half g_xr[(size_t)MROWS * DDIM];       // x, K perm16
__device__ __half g_wlr[(size_t)DDIM * DDIM];       // Wl, K perm16
__device__ float  g_hp[(size_t)SPLITK * MROWS * DDIM];
__device__ __half g_h[(size_t)MROWS * DDIM];        // h, K perm16
__device__ float  g_pm[(size_t)MROWS * NT1];
__device__ float  g_pl[(size_t)MROWS * NT1];
__device__ float  g_mxv[MROWS];
__device__ float  g_rlv[MROWS];

// ---------------------------------------------------------------------------
__device__ __forceinline__ uint32_t smem_u32(const void* p) {
    uint32_t a;
    asm("{ .reg .u64 t; cvta.to.shared.u64 t, %1; cvt.u32.u64 %0, t; }"
        : "=r"(a) : "l"(p));
    return a;
}

// position of logical k (0..15) in perm16 order
__device__ __host__ __forceinline__ int pos16(int k) {
    return 4 * ((k >> 1) & 3) + 2 * ((k >> 3) & 1) + (k & 1);
}

__device__ __forceinline__ uint32_t pack2(float a, float b) {
    __half2 h = __floats2half2_rn(a, b);
    return *reinterpret_cast<uint32_t*>(&h);
}

__device__ __forceinline__ void mma_f16(float c[4],
                                        uint32_t a0, uint32_t a1,
                                        uint32_t a2, uint32_t a3,
                                        uint32_t b0, uint32_t b1) {
    asm volatile(
        "mma.sync.aligned.m16n8k16.row.col.f32.f16.f16.f32 "
        "{%0,%1,%2,%3}, {%4,%5,%6,%7}, {%8,%9}, {%0,%1,%2,%3};"
        : "+f"(c[0]), "+f"(c[1]), "+f"(c[2]), "+f"(c[3])
        : "r"(a0), "r"(a1), "r"(a2), "r"(a3), "r"(b0), "r"(b1));
}

constexpr int BK   = 64;              // fp16 elems per chunk
constexpr int AS   = 80;              // smem row stride (fp16) -> 160B, CF
constexpr int BS   = 80;
constexpr int A_STAGE = 128 * AS;
constexpr int B_STAGE = 256 * BS;
constexpr int NSTAGE  = 3;
constexpr int GEMM_SMEM = NSTAGE * (A_STAGE + B_STAGE) * 2;  // 184320 B

// ============================================================================
// gemm_f16:  C = A[M,K] @ B[N,K]^T  (A,B fp16 perm16; accum fp32)
// CTA tile 128x256, 8 warps (2m x 4n), warp 64x64, BK=64, 3-stage, 1 sync.
// epi_mode 0: p16 = half(exp(acc + aux[col] - m_tile)) perm16 into C16,
//             emit pm/pl partials. cols >= nvalidB contribute exp->0.
// epi_mode 2: C = acc + aux[col] (fp32)  ; epi_mode 3: C = acc (fp32)
// Kps = nominal K per z-slice; clamped against Ktot.
// ============================================================================
__global__ void __launch_bounds__(256, 1)
gemm_f16(const __half* __restrict__ A, long long lda,
         const __half* __restrict__ B, long long ldb,
         float* __restrict__ C, __half* __restrict__ C16,
         long long ldc, long long c_zstride,
         int Kps, int Ktot, int nvalidB,
         const float* __restrict__ aux, int epi_mode,
         float* __restrict__ pm, float* __restrict__ pl, int ntiles)
{
    extern __shared__ __half smh[];
    __half* sA = smh;
    __half* sB = smh + NSTAGE * A_STAGE;

    __shared__ float red_s[512];
    __shared__ float red2_s[512];

    const int tid  = threadIdx.x;
    const int wid  = tid >> 5;
    const int lane = tid & 31;
    const int g    = lane >> 2;
    const int t    = lane & 3;
    const int wm   = wid >> 2;
    const int wn   = wid & 3;
    const int m0   = blockIdx.x * 128;
    const int n0   = blockIdx.y * 256;

    const long long koff = (long long)blockIdx.z * Kps;
    const int Keff = min(Kps, (int)(Ktot - koff));
    A += koff;
    B += koff;
    C += (long long)blockIdx.z * c_zstride;

    auto load_tiles = [&](int c, int s) {
        const __half* Ab = A + (size_t)m0 * lda + (size_t)c * BK;
        const __half* Bb = B + (size_t)c * BK;
        const uint32_t sAa = smem_u32(sA + s * A_STAGE);
        const uint32_t sBa = smem_u32(sB + s * B_STAGE);
        #pragma unroll
        for (int q = 0; q < 4; ++q) {                 // A: 128 rows x 8 16B
            int idx = tid + q * 256;
            int r = idx >> 3, j = idx & 7;
            const __half* gp = Ab + (size_t)r * lda + j * 8;
            uint32_t da = sAa + (uint32_t)(r * AS + j * 8) * 2;
            asm volatile("cp.async.cg.shared.global [%0], [%1], 16;"
                         :: "r"(da), "l"(gp) : "memory");
        }
        #pragma unroll
        for (int q = 0; q < 8; ++q) {                 // B: 256 rows x 8 16B
            int idx = tid + q * 256;
            int r = idx >> 3, j = idx & 7;
            int gn = n0 + r;
            int ok = (gn < nvalidB);
            const __half* gq = Bb + (size_t)(ok ? gn : 0) * ldb + j * 8;
            uint32_t db = sBa + (uint32_t)(r * BS + j * 8) * 2;
            int sz = ok ? 16 : 0;
            asm volatile("cp.async.cg.shared.global [%0], [%1], 16, %2;"
                         :: "r"(db), "l"(gq), "r"(sz) : "memory");
        }
        asm volatile("cp.async.commit_group;" ::: "memory");
    };

    float acc[4][8][4];
    #pragma unroll
    for (int i = 0; i < 4; ++i)
        #pragma unroll
        for (int j = 0; j < 8; ++j)
            #pragma unroll
            for (int k = 0; k < 4; ++k) acc[i][j][k] = 0.f;

    const int NCH = Keff / BK;
    load_tiles(0, 0);
    if (NCH > 1) load_tiles(1, 1);

    for (int c = 0; c < NCH; ++c) {
        if (c + 1 < NCH) {
            asm volatile("cp.async.wait_group 1;" ::: "memory");
        } else {
            asm volatile("cp.async.wait_group 0;" ::: "memory");
        }
        __syncthreads();
        if (c + 2 < NCH) load_tiles(c + 2, (c + 2) % NSTAGE);

        const int s = c % NSTAGE;
        const __half* tA = sA + s * A_STAGE;
        const __half* tB = sB + s * B_STAGE;

        #pragma unroll
        for (int ks = 0; ks < 4; ++ks) {              // 4 x k16 per BK=64
            const int kb = ks * 16 + 4 * t;           // perm16 pair offset
            uint2 bf[8];
            #pragma unroll
            for (int ni = 0; ni < 8; ++ni) {
                int col = wn * 64 + ni * 8 + g;
                bf[ni] = *reinterpret_cast<const uint2*>(tB + col * BS + kb);
            }
            #pragma unroll
            for (int mi = 0; mi < 4; ++mi) {
                int rr = wm * 64 + mi * 16 + g;
                uint2 qa = *reinterpret_cast<const uint2*>(tA + rr * AS + kb);
                uint2 qb = *reinterpret_cast<const uint2*>(tA + (rr + 8) * AS + kb);
                #pragma unroll
                for (int ni = 0; ni < 8; ++ni)
                    mma_f16(acc[mi][ni], qa.x, qb.x, qa.y, qb.y,
                            bf[ni].x, bf[ni].y);
            }
        }
    }

    if (epi_mode == 0) {
        // ---- pass 1: bias + mask into acc, track per-thread tile max ----
        float mx8[4][2];
        #pragma unroll
        for (int mi = 0; mi < 4; ++mi) { mx8[mi][0] = -3e38f; mx8[mi][1] = -3e38f; }
        #pragma unroll
        for (int mi = 0; mi < 4; ++mi) {
            #pragma unroll
            for (int ni = 0; ni < 8; ++ni) {
                const int col = n0 + wn * 64 + ni * 8 + 2 * t;
                float b0 = (col     < nvalidB) ? aux[col]     : 0.f;
                float b1 = (col + 1 < nvalidB) ? aux[col + 1] : 0.f;
                float v0 = acc[mi][ni][0] + b0, v1 = acc[mi][ni][1] + b1;
                float v2 = acc[mi][ni][2] + b0, v3 = acc[mi][ni][3] + b1;
                if (col     >= nvalidB) { v0 = -1e30f; v2 = -1e30f; }
                if (col + 1 >= nvalidB) { v1 = -1e30f; v3 = -1e30f; }
                acc[mi][ni][0] = v0; acc[mi][ni][1] = v1;
                acc[mi][ni][2] = v2; acc[mi][ni][3] = v3;
                mx8[mi][0] = fmaxf(mx8[mi][0], fmaxf(v0, v1));
                mx8[mi][1] = fmaxf(mx8[mi][1], fmaxf(v2, v3));
            }
        }
        #pragma unroll
        for (int mi = 0; mi < 4; ++mi)
            #pragma unroll
            for (int h = 0; h < 2; ++h) {
                float m = mx8[mi][h];
                m = fmaxf(m, __shfl_xor_sync(0xffffffffu, m, 1));
                m = fmaxf(m, __shfl_xor_sync(0xffffffffu, m, 2));
                mx8[mi][h] = m;
            }
        if (t == 0) {
            #pragma unroll
            for (int mi = 0; mi < 4; ++mi)
                #pragma unroll
                for (int h = 0; h < 2; ++h)
                    red_s[(wm * 64 + mi * 16 + h * 8 + g) * 4 + wn] = mx8[mi][h];
        }
        __syncthreads();
        float mf[4][2];
        #pragma unroll
        for (int mi = 0; mi < 4; ++mi)
            #pragma unroll
            for (int h = 0; h < 2; ++h) {
                int rl = wm * 64 + mi * 16 + h * 8 + g;
                mf[mi][h] = fmaxf(fmaxf(red_s[rl * 4 + 0], red_s[rl * 4 + 1]),
                                  fmaxf(red_s[rl * 4 + 2], red_s[rl * 4 + 3]));
            }

        // ---- pass 2: exp, fp16 perm16 store, accumulate l partials ----
        float s8[4][2];
        #pragma unroll
        for (int mi = 0; mi < 4; ++mi) { s8[mi][0] = 0.f; s8[mi][1] = 0.f; }
        #pragma unroll
        for (int mi = 0; mi < 4; ++mi) {
            const int rr = m0 + wm * 64 + mi * 16 + g;
            #pragma unroll
            for (int j = 0; j < 4; ++j) {             // pair ni = 2j, 2j+1
                const int base = n0 + wn * 64 + j * 16;   // 16-col group
                // row rr: logical cols 2t,2t+1 (ni=2j) and 2t+8,2t+9 (ni=2j+1)
                float e00 = __expf(acc[mi][2*j][0]   - mf[mi][0]);
                float e01 = __expf(acc[mi][2*j][1]   - mf[mi][0]);
                float e10 = __expf(acc[mi][2*j+1][0] - mf[mi][0]);
                float e11 = __expf(acc[mi][2*j+1][1] - mf[mi][0]);
                s8[mi][0] += (e00 + e01) + (e10 + e11);
                *reinterpret_cast<uint2*>(C16 + (size_t)rr * ldc + base + 4*t) =
                    make_uint2(pack2(e00, e01), pack2(e10, e11));
                // row rr+8
                float f00 = __expf(acc[mi][2*j][2]   - mf[mi][1]);
                float f01 = __expf(acc[mi][2*j][3]   - mf[mi][1]);
                float f10 = __expf(acc[mi][2*j+1][2] - mf[mi][1]);
                float f11 = __expf(acc[mi][2*j+1][3] - mf[mi][1]);
                s8[mi][1] += (f00 + f01) + (f10 + f11);
                *reinterpret_cast<uint2*>(C16 + (size_t)(rr + 8) * ldc + base + 4*t) =
                    make_uint2(pack2(f00, f01), pack2(f10, f11));
            }
        }
        #pragma unroll
        for (int mi = 0; mi < 4; ++mi)
            #pragma unroll
            for (int h = 0; h < 2; ++h) {
                float s = s8[mi][h];
                s += __shfl_xor_sync(0xffffffffu, s, 1);
                s += __shfl_xor_sync(0xffffffffu, s, 2);
                s8[mi][h] = s;
            }
        if (t == 0) {
            #pragma unroll
            for (int mi = 0; mi < 4; ++mi)
                #pragma unroll
                for (int h = 0; h < 2; ++h)
                    red2_s[(wm * 64 + mi * 16 + h * 8 + g) * 4 + wn] = s8[mi][h];
        }
        __syncthreads();
        if (wn == 0 && t == 0) {
            #pragma unroll
            for (int mi = 0; mi < 4; ++mi)
                #pragma unroll
                for (int h = 0; h < 2; ++h) {
                    int rl = wm * 64 + mi * 16 + h * 8 + g;
                    float l = red2_s[rl * 4 + 0] + red2_s[rl * 4 + 1]
                            + red2_s[rl * 4 + 2] + red2_s[rl * 4 + 3];
                    size_t idx = (size_t)(m0 + rl) * ntiles + blockIdx.y;
                    pm[idx] = mf[mi][h];
                    pl[idx] = l;
                }
        }
        return;
    }

    // ---- epilogue modes 2/3: fp32 float2 stores ----
    #pragma unroll
    for (int mi = 0; mi < 4; ++mi) {
        const int rr = m0 + wm * 64 + mi * 16 + g;
        #pragma unroll
        for (int ni = 0; ni < 8; ++ni) {
            const int col = n0 + wn * 64 + ni * 8 + 2 * t;
            float v0 = acc[mi][ni][0], v1 = acc[mi][ni][1];
            float v2 = acc[mi][ni][2], v3 = acc[mi][ni][3];
            if (epi_mode == 2) {
                float b0 = aux[col], b1 = aux[col + 1];
                v0 += b0; v1 += b1; v2 += b0; v3 += b1;
            }
            *reinterpret_cast<float2*>(C + (size_t)rr * ldc + col) =
                make_float2(v0, v1);
            *reinterpret_cast<float2*>(C + (size_t)(rr + 8) * ldc + col) =
                make_float2(v2, v3);
        }
    }
}

// ============================================================================
// combine_stats: per row, M and R=1/l from NT1 (m_t, l_t) tile partials.
// ============================================================================
__global__ void __launch_bounds__(256)
combine_stats(const float* __restrict__ pm, const float* __restrict__ pl,
              float* __restrict__ mxv, float* __restrict__ rlv)
{
    const int row  = blockIdx.x * 8 + (threadIdx.x >> 5);
    const int lane = threadIdx.x & 31;
    const float* pmr = pm + (size_t)row * NT1;
    const float* plr = pl + (size_t)row * NT1;

    float m = -3e38f;
    for (int i = lane; i < NT1; i += 32) m = fmaxf(m, pmr[i]);
    #pragma unroll
    for (int o = 16; o > 0; o >>= 1)
        m = fmaxf(m, __shfl_xor_sync(0xffffffffu, m, o));

    float l = 0.f;
    for (int i = lane; i < NT1; i += 32) l += plr[i] * __expf(pmr[i] - m);
    #pragma unroll
    for (int o = 16; o > 0; o >>= 1)
        l += __shfl_xor_sync(0xffffffffu, l, o);

    if (lane == 0) { mxv[row] = m; rlv[row] = 1.0f / l; }
}

// ============================================================================
// rescale: p *= exp(m_tile - M) * R   (fp32 math, fp16 in/out, in place)
// One CTA per row; 8 halves per thread-step.
// ============================================================================
__global__ void __launch_bounds__(256)
rescale(__half* __restrict__ P, const float* __restrict__ pm,
        const float* __restrict__ mxv, const float* __restrict__ rlv)
{
    const int row = blockIdx.x;
    __half* op = P + (size_t)row * VPAD;
    const float* pmr = pm + (size_t)row * NT1;
    const float M = mxv[row];
    const float R = rlv[row];

    for (int i = threadIdx.x; i < VPAD / 8; i += 256) {
        const int tile = (i * 8) >> 8;
        const float s = __expf(pmr[tile] - M) * R;
        uint4 v = reinterpret_cast<const uint4*>(op)[i];
        const __half2* h = reinterpret_cast<const __half2*>(&v);
        uint32_t o[4];
        #pragma unroll
        for (int q = 0; q < 4; ++q) {
            float2 f = __half22float2(h[q]);
            o[q] = pack2(f.x * s, f.y * s);
        }
        reinterpret_cast<uint4*>(op)[i] = make_uint4(o[0], o[1], o[2], o[3]);
    }
}

// ============================================================================
// prep: fp32 -> fp16 perm16 copy (16 consecutive elems per thread)
// ============================================================================
__global__ void __launch_bounds__(256)
half_copy_perm(const float* __restrict__ in, __half* __restrict__ out,
               long long n)
{
    long long i16 = ((long long)blockIdx.x * 256 + threadIdx.x) * 16;
    if (i16 >= n) return;
    float e[16];
    #pragma unroll
    for (int q = 0; q < 4; ++q) {
        float4 v = *reinterpret_cast<const float4*>(in + i16 + q * 4);
        e[q * 4 + 0] = v.x; e[q * 4 + 1] = v.y;
        e[q * 4 + 2] = v.z; e[q * 4 + 3] = v.w;
    }
    uint32_t o[8];
    #pragma unroll
    for (int tq = 0; tq < 4; ++tq) {
        o[tq * 2 + 0] = pack2(e[2 * tq],     e[2 * tq + 1]);
        o[tq * 2 + 1] = pack2(e[2 * tq + 8], e[2 * tq + 9]);
    }
    uint4* dst = reinterpret_cast<uint4*>(out + i16);
    dst[0] = make_uint4(o[0], o[1], o[2], o[3]);
    dst[1] = make_uint4(o[4], o[5], o[6], o[7]);
}

// ============================================================================
// transpose_wv: wvt[d, perm16(v)] = half(Wv[v, d]), zero-padded to VPAD
// ============================================================================
__global__ void __launch_bounds__(256)
transpose_wv(const float* __restrict__ Wv, __half* __restrict__ WvT)
{
    __shared__ float tt[32][33];
    const int v0 = blockIdx.x * 32;
    const int d0 = blockIdx.y * 32;
    const int tx = threadIdx.x & 31;
    const int ty = threadIdx.x >> 5;
    #pragma unroll
    for (int i = 0; i < 32; i += 8) {
        int v = v0 + ty + i;
        tt[ty + i][tx] = (v < VOCAB) ? Wv[(size_t)v * DDIM + d0 + tx] : 0.f;
    }
    __syncthreads();
    const int pcol = v0 + (tx & 16) + pos16(tx & 15);
    #pragma unroll
    for (int i = 0; i < 32; i += 8)
        WvT[(size_t)(d0 + ty + i) * VPAD + pcol] = __float2half_rn(tt[tx][ty + i]);
}

// ============================================================================
// reduce_splitk: h = half(sum_z hp[z]), perm16 packed (16 elems/thread)
// ============================================================================
__global__ void __launch_bounds__(256)
reduce_splitk(const float* __restrict__ hp, __half* __restrict__ h)
{
    const size_t MD = (size_t)MROWS * DDIM;
    size_t i16 = ((size_t)blockIdx.x * 256 + threadIdx.x) * 16;
    float e[16];
    #pragma unroll
    for (int q = 0; q < 4; ++q) {
        float4 v = *reinterpret_cast<const float4*>(hp + i16 + q * 4);
        e[q * 4 + 0] = v.x; e[q * 4 + 1] = v.y;
        e[q * 4 + 2] = v.z; e[q * 4 + 3] = v.w;
    }
    #pragma unroll
    for (int z = 1; z < SPLITK; ++z) {
        #pragma unroll
        for (int q = 0; q < 4; ++q) {
            float4 v = *reinterpret_cast<const float4*>(hp + z * MD + i16 + q * 4);
            e[q * 4 + 0] += v.x; e[q * 4 + 1] += v.y;
            e[q * 4 + 2] += v.z; e[q * 4 + 3] += v.w;
        }
    }
    uint32_t o[8];
    #pragma unroll
    for (int tq = 0; tq < 4; ++tq) {
        o[tq * 2 + 0] = pack2(e[2 * tq],     e[2 * tq + 1]);
        o[tq * 2 + 1] = pack2(e[2 * tq + 8], e[2 * tq + 9]);
    }
    uint4* dst = reinterpret_cast<uint4*>(h + i16);
    dst[0] = make_uint4(o[0], o[1], o[2], o[3]);
    dst[1] = make_uint4(o[4], o[5], o[6], o[7]);
}

// ============================================================================
// host launcher
// ============================================================================
extern "C" void kernel_launch(void* const* d_in, const int* in_sizes, int n_in,
                              void* d_out, int out_size)
{
    const float* x  = (const float*)d_in[0];
    const float* Wv = (const float*)d_in[1];
    const float* bv = (const float*)d_in[2];
    const float* Wl = (const float*)d_in[3];
    const float* bl = (const float*)d_in[4];
    float* out = (float*)d_out;

    void *p_p16, *p_wvt, *p_wvr, *p_xr, *p_wlr, *p_hp, *p_h,
         *p_pm, *p_pl, *p_mx, *p_rl;
    cudaGetSymbolAddress(&p_p16, g_p16);
    cudaGetSymbolAddress(&p_wvt, g_wvt);
    cudaGetSymbolAddress(&p_wvr, g_wvr);
    cudaGetSymbolAddress(&p_xr,  g_xr);
    cudaGetSymbolAddress(&p_wlr, g_wlr);
    cudaGetSymbolAddress(&p_hp,  g_hp);
    cudaGetSymbolAddress(&p_h,   g_h);
    cudaGetSymbolAddress(&p_pm,  g_pm);
    cudaGetSymbolAddress(&p_pl,  g_pl);
    cudaGetSymbolAddress(&p_mx,  g_mxv);
    cudaGetSymbolAddress(&p_rl,  g_rlv);
    __half* p16 = (__half*)p_p16;
    __half* wvt = (__half*)p_wvt;
    __half* wvr = (__half*)p_wvr;
    __half* xr  = (__half*)p_xr;
    __half* wlr = (__half*)p_wlr;
    float*  hp  = (float*)p_hp;
    __half* h   = (__half*)p_h;
    float*  pm  = (float*)p_pm;
    float*  pl  = (float*)p_pl;
    float*  mxv = (float*)p_mx;
    float*  rlv = (float*)p_rl;

    static bool attr_set = false;
    if (!attr_set) {
        cudaFuncSetAttribute(gemm_f16,
            cudaFuncAttributeMaxDynamicSharedMemorySize, GEMM_SMEM);
        attr_set = true;
    }

    // 1) prep: fp16 perm16 copies + transpose
    const long long nX = (long long)MROWS * DDIM;
    const long long nL = (long long)DDIM * DDIM;
    const long long nV = (long long)VOCAB * DDIM;
    half_copy_perm<<<(int)((nX / 16 + 255) / 256), 256>>>(x, xr, nX);
    half_copy_perm<<<(int)((nL / 16 + 255) / 256), 256>>>(Wl, wlr, nL);
    half_copy_perm<<<(int)((nV / 16 + 255) / 256), 256>>>(Wv, wvr, nV);
    transpose_wv<<<dim3(VPAD / 32, DDIM / 32), 256>>>(Wv, wvt);

    // 2) GEMM1: p_tile = exp(x@Wv^T + bv - m_tile) fp16 perm16, + pm/pl
    gemm_f16<<<dim3(MROWS / 128, NT1, 1), 256, GEMM_SMEM>>>(
        xr, DDIM, wvr, DDIM, nullptr, p16, VPAD, 0,
        DDIM, DDIM, VOCAB, bv, 0, pm, pl, NT1);

    // 3) combine -> M, 1/l
    combine_stats<<<MROWS / 8, 256>>>(pm, pl, mxv, rlv);

    // 4) rescale p in place
    rescale<<<MROWS, 256>>>(p16, pm, mxv, rlv);

    // 5) hp[z] = p @ wvt^T (split-K=6, clamped), h = half(sum) perm16
    gemm_f16<<<dim3(MROWS / 128, DDIM / 256, SPLITK), 256, GEMM_SMEM>>>(
        p16, VPAD, wvt, VPAD, hp, nullptr, DDIM, (long long)MROWS * DDIM,
        KSPL, VPAD, DDIM, nullptr, 3, nullptr, nullptr, 0);
    reduce_splitk<<<MROWS * DDIM / 4096, 256>>>(hp, h);

    // 6) out = h @ wlr^T + bl
    gemm_f16<<<dim3(MROWS / 128, DDIM / 256, 1), 256, GEMM_SMEM>>>(
        h, DDIM, wlr, DDIM, out, nullptr, DDIM, 0,
        DDIM, DDIM, DDIM, bl, 2, nullptr, nullptr, 0);
}